// round 4
// baseline (speedup 1.0000x reference)
#include <cuda_runtime.h>
#include <math.h>

#define N_NODES 10000
#define N_EDGES 160000
#define E_TOT   170000   // edges + self loops
#define IN_CH   1030
#define HC      1024
#define HID     256
#define HEADS   4
#define OUT_CH  49

// ---------------- device scratch (no allocations allowed) ----------------
__device__ float g_xl[(size_t)N_NODES * HC];
__device__ float g_xr[(size_t)N_NODES * HC];
__device__ float g_h [(size_t)N_NODES * HC];
__device__ float g_cls[(size_t)N_NODES * HID];
__device__ int      g_src[E_TOT];
__device__ int      g_dst[E_TOT];
__device__ float    g_esc[E_TOT * 4];
__device__ unsigned g_emax[N_NODES * 4];
__device__ float    g_den [N_NODES * 4];
__device__ int g_cnt[N_NODES];
__device__ int g_rowptr[N_NODES + 1];
__device__ int g_cursor[N_NODES];
__device__ int g_perm[E_TOT];
__device__ int g_ei_is64;

// ordered-uint encoding for float atomicMax
__device__ __forceinline__ unsigned f2u(float f) {
    unsigned u = __float_as_uint(f);
    return (u & 0x80000000u) ? ~u : (u | 0x80000000u);
}
__device__ __forceinline__ float u2f(unsigned u) {
    return (u & 0x80000000u) ? __uint_as_float(u & 0x7fffffffu) : __uint_as_float(~u);
}

// ---------------- edge_index dtype detection (int32 vs int64) ----------------
__global__ void k_detect(const unsigned long long* __restrict__ ei64) {
    // If data is int64 node ids (< 10000), every 8-byte word has a zero high half.
    // If data is int32 pairs, high halves are the odd-position edge ids (rarely 0).
    int is64 = 1;
    for (int i = 0; i < 64; i++)
        if (ei64[i] >= (1ULL << 32)) { is64 = 0; break; }
    g_ei_is64 = is64;
}

// ---------------- CSR build ----------------
__global__ void k_zero_csr() {
    int i = blockIdx.x * blockDim.x + threadIdx.x;
    if (i < N_NODES) g_cnt[i] = 0;
}

__global__ void k_build(const void* __restrict__ ei) {
    int i = blockIdx.x * blockDim.x + threadIdx.x;
    if (i >= E_TOT) return;
    int s, d;
    if (i < N_EDGES) {
        if (g_ei_is64) {
            const long long* p = (const long long*)ei;
            s = (int)p[i];
            d = (int)p[N_EDGES + i];
        } else {
            const int* p = (const int*)ei;
            s = p[i];
            d = p[N_EDGES + i];
        }
    } else {
        s = d = i - N_EDGES;  // self loop
    }
    // clamp: any residual interpretation mismatch fails cleanly, not with a trap
    if ((unsigned)s >= N_NODES) s = 0;
    if ((unsigned)d >= N_NODES) d = 0;
    g_src[i] = s;
    g_dst[i] = d;
    atomicAdd(&g_cnt[d], 1);
}

__global__ void k_scan() {  // single block, 1024 threads: exclusive scan of g_cnt
    __shared__ int wsum[32];
    __shared__ int carry_s;
    int tid = threadIdx.x;
    if (tid == 0) carry_s = 0;
    __syncthreads();
    for (int base = 0; base < N_NODES; base += 1024) {
        int i = base + tid;
        int v = (i < N_NODES) ? g_cnt[i] : 0;
        int incl = v;
        int lane = tid & 31, wid = tid >> 5;
        #pragma unroll
        for (int o = 1; o < 32; o <<= 1) {
            int t = __shfl_up_sync(0xffffffffu, incl, o);
            if (lane >= o) incl += t;
        }
        if (lane == 31) wsum[wid] = incl;
        __syncthreads();
        if (wid == 0) {
            int s = wsum[lane];
            #pragma unroll
            for (int o = 1; o < 32; o <<= 1) {
                int t = __shfl_up_sync(0xffffffffu, s, o);
                if (lane >= o) s += t;
            }
            wsum[lane] = s;
        }
        __syncthreads();
        int off = (wid > 0) ? wsum[wid - 1] : 0;
        int excl = carry_s + off + incl - v;
        if (i < N_NODES) { g_rowptr[i] = excl; g_cursor[i] = excl; }
        __syncthreads();
        if (tid == 0) carry_s += wsum[31];
        __syncthreads();
    }
    if (tid == 0) g_rowptr[N_NODES] = carry_s;
}

__global__ void k_scatter() {
    int e = blockIdx.x * blockDim.x + threadIdx.x;
    if (e >= E_TOT) return;
    int pos = atomicAdd(&g_cursor[g_dst[e]], 1);
    g_perm[pos] = e;
}

// ---------------- GEMM: C = A[M,K] @ B[K,N] + bias, optional ELU ----------------
// a_sel: 0 = external pointer A_ext, 1 = g_h
// c_sel: 0 = g_xl, 1 = g_xr, 2 = g_h, 3 = g_cls
__global__ __launch_bounds__(256)
void k_gemm(const float* __restrict__ A_ext, int a_sel, int c_sel,
            const float* __restrict__ B, const float* __restrict__ bias,
            int M, int K, int N, int act) {
    const float* A = (a_sel == 1) ? (const float*)g_h : A_ext;
    float* C = (c_sel == 0) ? g_xl : (c_sel == 1) ? g_xr : (c_sel == 2) ? g_h : g_cls;

    const int BM = 128, BN = 128, BK = 16;
    __shared__ float As[BK][BM];
    __shared__ float Bs[BK][BN];
    int tid = threadIdx.x;
    int bm = blockIdx.y * BM, bn = blockIdx.x * BN;
    int tx = tid % 16, ty = tid / 16;
    float acc[8][8];
    #pragma unroll
    for (int i = 0; i < 8; i++)
        #pragma unroll
        for (int j = 0; j < 8; j++) acc[i][j] = 0.f;

    for (int k0 = 0; k0 < K; k0 += BK) {
        #pragma unroll
        for (int t = 0; t < 8; t++) {
            int i = tid + t * 256;
            int r = i >> 4, c = i & 15;
            int gr = bm + r, gc = k0 + c;
            As[c][r] = (gr < M && gc < K) ? A[(size_t)gr * K + gc] : 0.f;
        }
        #pragma unroll
        for (int t = 0; t < 8; t++) {
            int i = tid + t * 256;
            int r = i >> 7, c = i & 127;
            int gr = k0 + r, gc = bn + c;
            Bs[r][c] = (gr < K && gc < N) ? B[(size_t)gr * N + gc] : 0.f;
        }
        __syncthreads();
        #pragma unroll
        for (int kk = 0; kk < BK; kk++) {
            float4 a0 = *(const float4*)&As[kk][ty * 8];
            float4 a1 = *(const float4*)&As[kk][ty * 8 + 4];
            float4 b0 = *(const float4*)&Bs[kk][tx * 8];
            float4 b1 = *(const float4*)&Bs[kk][tx * 8 + 4];
            float a[8] = {a0.x, a0.y, a0.z, a0.w, a1.x, a1.y, a1.z, a1.w};
            float b[8] = {b0.x, b0.y, b0.z, b0.w, b1.x, b1.y, b1.z, b1.w};
            #pragma unroll
            for (int i = 0; i < 8; i++)
                #pragma unroll
                for (int j = 0; j < 8; j++)
                    acc[i][j] = fmaf(a[i], b[j], acc[i][j]);
        }
        __syncthreads();
    }
    #pragma unroll
    for (int i = 0; i < 8; i++) {
        int row = bm + ty * 8 + i;
        if (row >= M) continue;
        #pragma unroll
        for (int j = 0; j < 8; j++) {
            int col = bn + tx * 8 + j;
            if (col >= N) continue;
            float v = acc[i][j] + bias[col];
            if (act == 1) v = v > 0.f ? v : expm1f(v);
            C[(size_t)row * N + col] = v;
        }
    }
}

// ---------------- edge attention scores: warp per edge ----------------
__global__ void k_edge_scores(const float* __restrict__ att) {
    int e = (blockIdx.x * blockDim.x + threadIdx.x) >> 5;
    int lane = threadIdx.x & 31;
    if (e >= E_TOT) return;
    const float* pl = g_xl + (size_t)g_src[e] * HC;
    const float* pr = g_xr + (size_t)g_dst[e] * HC;
    float acc[4] = {0.f, 0.f, 0.f, 0.f};
    #pragma unroll
    for (int i = 0; i < 32; i++) {
        int c = i * 32 + lane;
        float m = pl[c] + pr[c];
        m = m > 0.f ? m : 0.2f * m;          // leaky_relu(0.2)
        acc[i >> 3] += m * att[c];           // head = c/256, uniform per i
    }
    #pragma unroll
    for (int h = 0; h < 4; h++) {
        float v = acc[h];
        #pragma unroll
        for (int o = 16; o; o >>= 1) v += __shfl_xor_sync(0xffffffffu, v, o);
        if (lane == 0) g_esc[e * 4 + h] = v;
    }
}

__global__ void k_zero_soft() {
    int i = blockIdx.x * blockDim.x + threadIdx.x;
    if (i < N_NODES * 4) { g_emax[i] = 0u; g_den[i] = 0.f; }
}

__global__ void k_edge_max() {
    int i = blockIdx.x * blockDim.x + threadIdx.x;
    if (i >= E_TOT * 4) return;
    int e = i >> 2, h = i & 3;
    atomicMax(&g_emax[g_dst[e] * 4 + h], f2u(g_esc[i]));
}

__global__ void k_edge_exp() {
    int i = blockIdx.x * blockDim.x + threadIdx.x;
    if (i >= E_TOT * 4) return;
    int e = i >> 2, h = i & 3;
    int d = g_dst[e];
    float p = expf(g_esc[i] - u2f(g_emax[d * 4 + h]));
    g_esc[i] = p;
    atomicAdd(&g_den[d * 4 + h], p);
}

// ---------------- aggregation over CSR: block per dst node ----------------
__global__ __launch_bounds__(256)
void k_aggregate(const float* __restrict__ bias) {
    int n = blockIdx.x;
    int tid = threadIdx.x;
    float inv[4];
    #pragma unroll
    for (int h = 0; h < 4; h++) inv[h] = 1.f / (g_den[n * 4 + h] + 1e-16f);
    float acc[4] = {0.f, 0.f, 0.f, 0.f};
    int beg = g_rowptr[n], end = g_rowptr[n + 1];
    for (int j = beg; j < end; j++) {
        int e = g_perm[j];
        int s = g_src[e];
        float4 p = *(const float4*)&g_esc[e * 4];
        const float* row = g_xl + (size_t)s * HC;
        acc[0] = fmaf(p.x, row[tid      ], acc[0]);
        acc[1] = fmaf(p.y, row[tid + 256], acc[1]);
        acc[2] = fmaf(p.z, row[tid + 512], acc[2]);
        acc[3] = fmaf(p.w, row[tid + 768], acc[3]);
    }
    size_t base = (size_t)n * HC;
    g_h[base + tid      ] = acc[0] * inv[0] + bias[tid      ];
    g_h[base + tid + 256] = acc[1] * inv[1] + bias[tid + 256];
    g_h[base + tid + 512] = acc[2] * inv[2] + bias[tid + 512];
    g_h[base + tid + 768] = acc[3] * inv[3] + bias[tid + 768];
}

// ---------------- LayerNorm + ELU, in place on g_h ----------------
__global__ __launch_bounds__(256)
void k_ln_elu(const float* __restrict__ w, const float* __restrict__ b) {
    int n = blockIdx.x, tid = threadIdx.x;
    size_t base = (size_t)n * HC;
    float v[4];
    float s = 0.f, s2 = 0.f;
    #pragma unroll
    for (int i = 0; i < 4; i++) {
        v[i] = g_h[base + tid + i * 256];
        s += v[i];
        s2 += v[i] * v[i];
    }
    __shared__ float rs[8], rs2[8];
    int lane = tid & 31, wid = tid >> 5;
    #pragma unroll
    for (int o = 16; o; o >>= 1) {
        s  += __shfl_xor_sync(0xffffffffu, s,  o);
        s2 += __shfl_xor_sync(0xffffffffu, s2, o);
    }
    if (lane == 0) { rs[wid] = s; rs2[wid] = s2; }
    __syncthreads();
    if (tid == 0) {
        float a = 0.f, a2 = 0.f;
        #pragma unroll
        for (int i = 0; i < 8; i++) { a += rs[i]; a2 += rs2[i]; }
        rs[0] = a; rs2[0] = a2;
    }
    __syncthreads();
    float mu = rs[0] * (1.f / HC);
    float var = rs2[0] * (1.f / HC) - mu * mu;
    float r = rsqrtf(var + 1e-5f);
    #pragma unroll
    for (int i = 0; i < 4; i++) {
        int c = tid + i * 256;
        float y = (v[i] - mu) * r * w[c] + b[c];
        g_h[base + c] = y > 0.f ? y : expm1f(y);
    }
}

// ---------------- classifier layer 2: [N,256] @ [256,49] ----------------
__global__ void k_cls2(const float* __restrict__ w2, const float* __restrict__ b2,
                       float* __restrict__ out) {
    __shared__ float sh[HID];
    int n = blockIdx.x;
    for (int i = threadIdx.x; i < HID; i += 64) sh[i] = g_cls[(size_t)n * HID + i];
    __syncthreads();
    int t = threadIdx.x;
    if (t < OUT_CH) {
        float a = b2[t];
        for (int k = 0; k < HID; k++) a = fmaf(sh[k], w2[k * OUT_CH + t], a);
        out[(size_t)n * OUT_CH + t] = a;
    }
}

// ---------------- launch ----------------
extern "C" void kernel_launch(void* const* d_in, const int* in_sizes, int n_in,
                              void* d_out, int out_size) {
    // Canonical slots: 0:x 1:ei 2:c1_wl 3:c1_bl 4:c1_wr 5:c1_br 6:c1_att 7:c1_bias
    // 8:ln1_w 9:ln1_b 10:c2_wl 11:c2_bl 12:c2_wr 13:c2_br 14:c2_att 15:c2_bias
    // 16:ln2_w 17:ln2_b 18:cls_w1 19:cls_b1 20:cls_w2 21:cls_b2
    static const int MAP_INSERT[22] =
        {0,1,2,3,4,5,6,7,8,9,10,11,12,13,14,15,16,17,18,19,20,21};
    static const int MAP_ALPHA[22] =
        {21, 16, 4, 2, 5, 3, 0, 1, 18, 17,
         10, 8, 11, 9, 6, 7, 20, 19, 14, 12, 15, 13};

    const int* map = MAP_INSERT;
    if (n_in >= 22 && in_sizes[0] != N_NODES * IN_CH && in_sizes[21] == N_NODES * IN_CH)
        map = MAP_ALPHA;

    const float* x       = (const float*)d_in[map[0]];
    const void*  ei      = d_in[map[1]];
    const float* c1_wl   = (const float*)d_in[map[2]];
    const float* c1_bl   = (const float*)d_in[map[3]];
    const float* c1_wr   = (const float*)d_in[map[4]];
    const float* c1_br   = (const float*)d_in[map[5]];
    const float* c1_att  = (const float*)d_in[map[6]];
    const float* c1_bias = (const float*)d_in[map[7]];
    const float* ln1_w   = (const float*)d_in[map[8]];
    const float* ln1_b   = (const float*)d_in[map[9]];
    const float* c2_wl   = (const float*)d_in[map[10]];
    const float* c2_bl   = (const float*)d_in[map[11]];
    const float* c2_wr   = (const float*)d_in[map[12]];
    const float* c2_br   = (const float*)d_in[map[13]];
    const float* c2_att  = (const float*)d_in[map[14]];
    const float* c2_bias = (const float*)d_in[map[15]];
    const float* ln2_w   = (const float*)d_in[map[16]];
    const float* ln2_b   = (const float*)d_in[map[17]];
    const float* cls_w1  = (const float*)d_in[map[18]];
    const float* cls_b1  = (const float*)d_in[map[19]];
    const float* cls_w2  = (const float*)d_in[map[20]];
    const float* cls_b2  = (const float*)d_in[map[21]];
    float* out = (float*)d_out;

    // edge_index dtype detect + CSR build (shared by both conv layers)
    k_detect<<<1, 1>>>((const unsigned long long*)ei);
    k_zero_csr<<<(N_NODES + 255) / 256, 256>>>();
    k_build<<<(E_TOT + 255) / 256, 256>>>(ei);
    k_scan<<<1, 1024>>>();
    k_scatter<<<(E_TOT + 255) / 256, 256>>>();

    dim3 gc(HC / 128, (N_NODES + 127) / 128);
    int eb  = (E_TOT + 7) / 8;           // warp per edge, 8 warps/block
    int e4b = (E_TOT * 4 + 255) / 256;
    int zb  = (N_NODES * 4 + 255) / 256;

    // ---- conv1 ----
    k_gemm<<<gc, 256>>>(x, 0, 0, c1_wl, c1_bl, N_NODES, IN_CH, HC, 0);
    k_gemm<<<gc, 256>>>(x, 0, 1, c1_wr, c1_br, N_NODES, IN_CH, HC, 0);
    k_edge_scores<<<eb, 256>>>(c1_att);
    k_zero_soft<<<zb, 256>>>();
    k_edge_max<<<e4b, 256>>>();
    k_edge_exp<<<e4b, 256>>>();
    k_aggregate<<<N_NODES, 256>>>(c1_bias);
    k_ln_elu<<<N_NODES, 256>>>(ln1_w, ln1_b);

    // ---- conv2 ----
    k_gemm<<<gc, 256>>>(nullptr, 1, 0, c2_wl, c2_bl, N_NODES, HC, HC, 0);
    k_gemm<<<gc, 256>>>(nullptr, 1, 1, c2_wr, c2_br, N_NODES, HC, HC, 0);
    k_edge_scores<<<eb, 256>>>(c2_att);
    k_zero_soft<<<zb, 256>>>();
    k_edge_max<<<e4b, 256>>>();
    k_edge_exp<<<e4b, 256>>>();
    k_aggregate<<<N_NODES, 256>>>(c2_bias);
    k_ln_elu<<<N_NODES, 256>>>(ln2_w, ln2_b);

    // ---- classifier ----
    dim3 g1(HID / 128, (N_NODES + 127) / 128);
    k_gemm<<<g1, 256>>>(nullptr, 1, 3, cls_w1, cls_b1, N_NODES, HC, HID, 1);
    k_cls2<<<N_NODES, 64>>>(cls_w2, cls_b2, out);
}

// round 6
// speedup vs baseline: 2.4330x; 2.4330x over previous
#include <cuda_runtime.h>
#include <cuda_bf16.h>
#include <math.h>
#include <stdint.h>

#define N_NODES 10000
#define N_EDGES 160000
#define E_TOT   170000
#define IN_CH   1030
#define HC      1024
#define HID     256
#define OUT_CH  49
#define M_PAD   10112          // 79 * 128
#define KP1     1088           // conv1 K padded
#define KP2     1024           // conv2/cls1 K

// ---------------- device scratch ----------------
__device__ float g_xl[(size_t)N_NODES * HC];
__device__ float g_xr[(size_t)N_NODES * HC];
__device__ float g_h [(size_t)N_NODES * HC];
__device__ float g_cls[(size_t)N_NODES * HID];
__device__ __align__(128) __nv_bfloat16 g_ahi[(size_t)M_PAD * KP1];
__device__ __align__(128) __nv_bfloat16 g_alo[(size_t)M_PAD * KP1];
__device__ __align__(128) __nv_bfloat16 g_bhi[(size_t)HC * KP1];
__device__ __align__(128) __nv_bfloat16 g_blo[(size_t)HC * KP1];
__device__ int      g_src[E_TOT];
__device__ int      g_dst[E_TOT];
__device__ float    g_esc[E_TOT * 4];
__device__ unsigned g_emax[N_NODES * 4];
__device__ float    g_den [N_NODES * 4];
__device__ int g_cnt[N_NODES];
__device__ int g_rowptr[N_NODES + 1];
__device__ int g_cursor[N_NODES];
__device__ int g_perm[E_TOT];
__device__ int g_ei_is64;

__device__ __forceinline__ unsigned f2u(float f) {
    unsigned u = __float_as_uint(f);
    return (u & 0x80000000u) ? ~u : (u | 0x80000000u);
}
__device__ __forceinline__ float u2f(unsigned u) {
    return (u & 0x80000000u) ? __uint_as_float(u & 0x7fffffffu) : __uint_as_float(~u);
}

// ---------------- async copy helpers (sm_80 baseline, safe on sm_103) --------
__device__ __forceinline__ uint32_t smem_u32(const void* p) {
    uint32_t a;
    asm("{ .reg .u64 t; cvta.to.shared.u64 t, %1; cvt.u32.u64 %0, t; }" : "=r"(a) : "l"(p));
    return a;
}
__device__ __forceinline__ void cp_async16(uint32_t dst, const void* src) {
    asm volatile("cp.async.cg.shared.global [%0], [%1], 16;" :: "r"(dst), "l"(src));
}
#define CP_COMMIT() asm volatile("cp.async.commit_group;")
#define CP_WAIT0()  asm volatile("cp.async.wait_group 0;" ::: "memory")
#define CP_WAIT1()  asm volatile("cp.async.wait_group 1;" ::: "memory")

__device__ __forceinline__ void mma16816(float* c, const uint32_t* a,
                                         uint32_t b0, uint32_t b1) {
    asm volatile(
        "mma.sync.aligned.m16n8k16.row.col.f32.bf16.bf16.f32 "
        "{%0,%1,%2,%3}, {%4,%5,%6,%7}, {%8,%9}, {%0,%1,%2,%3};"
        : "+f"(c[0]), "+f"(c[1]), "+f"(c[2]), "+f"(c[3])
        : "r"(a[0]), "r"(a[1]), "r"(a[2]), "r"(a[3]), "r"(b0), "r"(b1));
}

// ---------------- fp32 -> split bf16 conversion ----------------
__global__ void k_cvt_a(const float* __restrict__ A_ext, int a_sel,
                        int M_real, int K_real, int K_pad, int M_use) {
    const float* A = (a_sel == 1) ? (const float*)g_h : A_ext;
    size_t idx = (size_t)blockIdx.x * blockDim.x + threadIdx.x;
    size_t tot = (size_t)M_use * K_pad;
    if (idx >= tot) return;
    int r = (int)(idx / K_pad), c = (int)(idx % K_pad);
    float x = (r < M_real && c < K_real) ? A[(size_t)r * K_real + c] : 0.f;
    __nv_bfloat16 hi = __float2bfloat16_rn(x);
    __nv_bfloat16 lo = __float2bfloat16_rn(x - __bfloat162float(hi));
    g_ahi[idx] = hi;
    g_alo[idx] = lo;
}

// B: [K_real, N] fp32 -> [N, K_pad] bf16 hi/lo (transposed, K contiguous)
__global__ void k_cvt_b(const float* __restrict__ B, int K_real, int N, int K_pad) {
    size_t idx = (size_t)blockIdx.x * blockDim.x + threadIdx.x;
    size_t tot = (size_t)N * K_pad;
    if (idx >= tot) return;
    int n = (int)(idx / K_pad), k = (int)(idx % K_pad);
    float x = (k < K_real) ? B[(size_t)k * N + n] : 0.f;
    __nv_bfloat16 hi = __float2bfloat16_rn(x);
    __nv_bfloat16 lo = __float2bfloat16_rn(x - __bfloat162float(hi));
    g_bhi[idx] = hi;
    g_blo[idx] = lo;
}

// ---------------- mma.sync split-bf16 GEMM ----------------
// smem stage: 4 tiles (A_hi, A_lo, B_hi, B_lo), each 128 rows x 32 bf16,
// row stride padded to 80B (conflict-free fragment LDS). stage = 40KB, x2.
#define ROWB   80
#define TIL    (128 * ROWB)     // 10240
#define STG    (4 * TIL)        // 40960
#define SMEM_MMA (2 * STG)

__device__ __forceinline__ void load_stage(uint32_t sb, int it, int tid,
                                           const __nv_bfloat16* s0, const __nv_bfloat16* s1,
                                           const __nv_bfloat16* s2, const __nv_bfloat16* s3,
                                           int K_pad) {
    uint32_t stage = sb + (uint32_t)(it & 1) * STG;
    int k0 = it * 32;
    const __nv_bfloat16* srcs[4] = {s0, s1, s2, s3};
    #pragma unroll
    for (int q = 0; q < 8; q++) {
        int id = tid + q * 256;            // 0..2047 : 4 tiles x 128 rows x 4 units
        int t = id >> 9, r = (id >> 2) & 127, u = id & 3;
        cp_async16(stage + t * TIL + r * ROWB + u * 16,
                   srcs[t] + (size_t)r * K_pad + k0 + u * 8);
    }
    CP_COMMIT();
}

__global__ __launch_bounds__(256)
void k_mma(int c_sel, const float* __restrict__ bias,
           int M, int N_tot, int K_pad, int act) {
    extern __shared__ char sm[];
    float* C = (c_sel == 0) ? g_xl : (c_sel == 1) ? g_xr : (c_sel == 2) ? g_h : g_cls;

    int tid = threadIdx.x, w = tid >> 5, l = tid & 31;
    int wm = w >> 1, wn = w & 1;                 // warp grid 4 x 2
    int bm = blockIdx.y * 128, bn = blockIdx.x * 128;
    uint32_t sb = smem_u32(sm);

    const __nv_bfloat16* sA_hi = g_ahi + (size_t)bm * K_pad;
    const __nv_bfloat16* sA_lo = g_alo + (size_t)bm * K_pad;
    const __nv_bfloat16* sB_hi = g_bhi + (size_t)bn * K_pad;
    const __nv_bfloat16* sB_lo = g_blo + (size_t)bn * K_pad;

    float acc[2][8][4];
    #pragma unroll
    for (int m = 0; m < 2; m++)
        #pragma unroll
        for (int n = 0; n < 8; n++)
            #pragma unroll
            for (int i = 0; i < 4; i++) acc[m][n][i] = 0.f;

    int nk = K_pad / 32;
    load_stage(sb, 0, tid, sA_hi, sA_lo, sB_hi, sB_lo, K_pad);
    load_stage(sb, 1, tid, sA_hi, sA_lo, sB_hi, sB_lo, K_pad);

    int arow = wm * 32 + (l >> 2);       // fragment row within A tile
    int acol = (l & 3) * 2;              // fragment k-col base
    int brow = wn * 64 + (l >> 2);       // fragment row within B tile

    for (int it = 0; it < nk; it++) {
        if (it == nk - 1) { CP_WAIT0(); } else { CP_WAIT1(); }
        __syncthreads();
        const char* st = sm + (it & 1) * STG;
        // 3 passes: (A_hi,B_hi), (A_hi,B_lo), (A_lo,B_hi)
        #pragma unroll
        for (int pass = 0; pass < 3; pass++) {
            const char* pA = st + ((pass < 2) ? 0 : TIL);
            const char* pB = st + ((pass == 1) ? 3 * TIL : 2 * TIL);
            #pragma unroll
            for (int k = 0; k < 2; k++) {
                int kc = k * 16 + acol;
                uint32_t a[2][4];
                #pragma unroll
                for (int m = 0; m < 2; m++) {
                    const char* ab = pA + (arow + m * 16) * ROWB + kc * 2;
                    a[m][0] = *(const uint32_t*)(ab);
                    a[m][1] = *(const uint32_t*)(ab + 8 * ROWB);
                    a[m][2] = *(const uint32_t*)(ab + 16);
                    a[m][3] = *(const uint32_t*)(ab + 8 * ROWB + 16);
                }
                #pragma unroll
                for (int n = 0; n < 8; n++) {
                    const char* bb = pB + (brow + n * 8) * ROWB + kc * 2;
                    uint32_t b0 = *(const uint32_t*)(bb);
                    uint32_t b1 = *(const uint32_t*)(bb + 16);
                    mma16816(acc[0][n], a[0], b0, b1);
                    mma16816(acc[1][n], a[1], b0, b1);
                }
            }
        }
        __syncthreads();
        if (it + 2 < nk) load_stage(sb, it + 2, tid, sA_hi, sA_lo, sB_hi, sB_lo, K_pad);
    }

    // epilogue: bias + optional ELU, fp32 out
    #pragma unroll
    for (int m = 0; m < 2; m++) {
        #pragma unroll
        for (int n = 0; n < 8; n++) {
            int col = bn + wn * 64 + n * 8 + (l & 3) * 2;
            float2 bv = *(const float2*)(bias + col);
            int r0 = bm + wm * 32 + m * 16 + (l >> 2);
            #pragma unroll
            for (int hh = 0; hh < 2; hh++) {
                int row = r0 + hh * 8;
                if (row < M) {
                    float vx = acc[m][n][hh * 2    ] + bv.x;
                    float vy = acc[m][n][hh * 2 + 1] + bv.y;
                    if (act == 1) {
                        vx = vx > 0.f ? vx : expm1f(vx);
                        vy = vy > 0.f ? vy : expm1f(vy);
                    }
                    *(float2*)(C + (size_t)row * N_tot + col) = make_float2(vx, vy);
                }
            }
        }
    }
}

// ---------------- edge_index dtype detection ----------------
__global__ void k_detect(const unsigned long long* __restrict__ ei64) {
    int is64 = 1;
    for (int i = 0; i < 64; i++)
        if (ei64[i] >= (1ULL << 32)) { is64 = 0; break; }
    g_ei_is64 = is64;
}

// ---------------- CSR build ----------------
__global__ void k_zero_csr() {
    int i = blockIdx.x * blockDim.x + threadIdx.x;
    if (i < N_NODES) g_cnt[i] = 0;
}

__global__ void k_build(const void* __restrict__ ei) {
    int i = blockIdx.x * blockDim.x + threadIdx.x;
    if (i >= E_TOT) return;
    int s, d;
    if (i < N_EDGES) {
        if (g_ei_is64) {
            const long long* p = (const long long*)ei;
            s = (int)p[i]; d = (int)p[N_EDGES + i];
        } else {
            const int* p = (const int*)ei;
            s = p[i]; d = p[N_EDGES + i];
        }
    } else {
        s = d = i - N_EDGES;
    }
    if ((unsigned)s >= N_NODES) s = 0;
    if ((unsigned)d >= N_NODES) d = 0;
    g_src[i] = s;
    g_dst[i] = d;
    atomicAdd(&g_cnt[d], 1);
}

__global__ void k_scan() {
    __shared__ int wsum[32];
    __shared__ int carry_s;
    int tid = threadIdx.x;
    if (tid == 0) carry_s = 0;
    __syncthreads();
    for (int base = 0; base < N_NODES; base += 1024) {
        int i = base + tid;
        int v = (i < N_NODES) ? g_cnt[i] : 0;
        int incl = v;
        int lane = tid & 31, wid = tid >> 5;
        #pragma unroll
        for (int o = 1; o < 32; o <<= 1) {
            int t = __shfl_up_sync(0xffffffffu, incl, o);
            if (lane >= o) incl += t;
        }
        if (lane == 31) wsum[wid] = incl;
        __syncthreads();
        if (wid == 0) {
            int s = wsum[lane];
            #pragma unroll
            for (int o = 1; o < 32; o <<= 1) {
                int t = __shfl_up_sync(0xffffffffu, s, o);
                if (lane >= o) s += t;
            }
            wsum[lane] = s;
        }
        __syncthreads();
        int off = (wid > 0) ? wsum[wid - 1] : 0;
        int excl = carry_s + off + incl - v;
        if (i < N_NODES) { g_rowptr[i] = excl; g_cursor[i] = excl; }
        __syncthreads();
        if (tid == 0) carry_s += wsum[31];
        __syncthreads();
    }
    if (tid == 0) g_rowptr[N_NODES] = carry_s;
}

__global__ void k_scatter() {
    int e = blockIdx.x * blockDim.x + threadIdx.x;
    if (e >= E_TOT) return;
    int pos = atomicAdd(&g_cursor[g_dst[e]], 1);
    g_perm[pos] = e;
}

// ---------------- edge attention scores ----------------
__global__ void k_edge_scores(const float* __restrict__ att) {
    int e = (blockIdx.x * blockDim.x + threadIdx.x) >> 5;
    int lane = threadIdx.x & 31;
    if (e >= E_TOT) return;
    const float* pl = g_xl + (size_t)g_src[e] * HC;
    const float* pr = g_xr + (size_t)g_dst[e] * HC;
    float acc[4] = {0.f, 0.f, 0.f, 0.f};
    #pragma unroll
    for (int i = 0; i < 32; i++) {
        int c = i * 32 + lane;
        float m = pl[c] + pr[c];
        m = m > 0.f ? m : 0.2f * m;
        acc[i >> 3] += m * att[c];
    }
    #pragma unroll
    for (int h = 0; h < 4; h++) {
        float v = acc[h];
        #pragma unroll
        for (int o = 16; o; o >>= 1) v += __shfl_xor_sync(0xffffffffu, v, o);
        if (lane == 0) g_esc[e * 4 + h] = v;
    }
}

__global__ void k_zero_soft() {
    int i = blockIdx.x * blockDim.x + threadIdx.x;
    if (i < N_NODES * 4) { g_emax[i] = 0u; g_den[i] = 0.f; }
}

__global__ void k_edge_max() {
    int i = blockIdx.x * blockDim.x + threadIdx.x;
    if (i >= E_TOT * 4) return;
    int e = i >> 2, h = i & 3;
    atomicMax(&g_emax[g_dst[e] * 4 + h], f2u(g_esc[i]));
}

__global__ void k_edge_exp() {
    int i = blockIdx.x * blockDim.x + threadIdx.x;
    if (i >= E_TOT * 4) return;
    int e = i >> 2, h = i & 3;
    int d = g_dst[e];
    float p = expf(g_esc[i] - u2f(g_emax[d * 4 + h]));
    g_esc[i] = p;
    atomicAdd(&g_den[d * 4 + h], p);
}

// ---------------- aggregation ----------------
__global__ __launch_bounds__(256)
void k_aggregate(const float* __restrict__ bias) {
    int n = blockIdx.x;
    int tid = threadIdx.x;
    float inv[4];
    #pragma unroll
    for (int h = 0; h < 4; h++) inv[h] = 1.f / (g_den[n * 4 + h] + 1e-16f);
    float acc[4] = {0.f, 0.f, 0.f, 0.f};
    int beg = g_rowptr[n], end = g_rowptr[n + 1];
    for (int j = beg; j < end; j++) {
        int e = g_perm[j];
        int s = g_src[e];
        float4 p = *(const float4*)&g_esc[e * 4];
        const float* row = g_xl + (size_t)s * HC;
        acc[0] = fmaf(p.x, row[tid      ], acc[0]);
        acc[1] = fmaf(p.y, row[tid + 256], acc[1]);
        acc[2] = fmaf(p.z, row[tid + 512], acc[2]);
        acc[3] = fmaf(p.w, row[tid + 768], acc[3]);
    }
    size_t base = (size_t)n * HC;
    g_h[base + tid      ] = acc[0] * inv[0] + bias[tid      ];
    g_h[base + tid + 256] = acc[1] * inv[1] + bias[tid + 256];
    g_h[base + tid + 512] = acc[2] * inv[2] + bias[tid + 512];
    g_h[base + tid + 768] = acc[3] * inv[3] + bias[tid + 768];
}

// ---------------- LayerNorm + ELU ----------------
__global__ __launch_bounds__(256)
void k_ln_elu(const float* __restrict__ w, const float* __restrict__ b) {
    int n = blockIdx.x, tid = threadIdx.x;
    size_t base = (size_t)n * HC;
    float v[4];
    float s = 0.f, s2 = 0.f;
    #pragma unroll
    for (int i = 0; i < 4; i++) {
        v[i] = g_h[base + tid + i * 256];
        s += v[i];
        s2 += v[i] * v[i];
    }
    __shared__ float rs[8], rs2[8];
    int lane = tid & 31, wid = tid >> 5;
    #pragma unroll
    for (int o = 16; o; o >>= 1) {
        s  += __shfl_xor_sync(0xffffffffu, s,  o);
        s2 += __shfl_xor_sync(0xffffffffu, s2, o);
    }
    if (lane == 0) { rs[wid] = s; rs2[wid] = s2; }
    __syncthreads();
    if (tid == 0) {
        float a = 0.f, a2 = 0.f;
        #pragma unroll
        for (int i = 0; i < 8; i++) { a += rs[i]; a2 += rs2[i]; }
        rs[0] = a; rs2[0] = a2;
    }
    __syncthreads();
    float mu = rs[0] * (1.f / HC);
    float var = rs2[0] * (1.f / HC) - mu * mu;
    float r = rsqrtf(var + 1e-5f);
    #pragma unroll
    for (int i = 0; i < 4; i++) {
        int c = tid + i * 256;
        float y = (v[i] - mu) * r * w[c] + b[c];
        g_h[base + c] = y > 0.f ? y : expm1f(y);
    }
}

// ---------------- classifier layer 2 ----------------
__global__ void k_cls2(const float* __restrict__ w2, const float* __restrict__ b2,
                       float* __restrict__ out) {
    __shared__ float sh[HID];
    int n = blockIdx.x;
    for (int i = threadIdx.x; i < HID; i += 64) sh[i] = g_cls[(size_t)n * HID + i];
    __syncthreads();
    int t = threadIdx.x;
    if (t < OUT_CH) {
        float a = b2[t];
        for (int k = 0; k < HID; k++) a = fmaf(sh[k], w2[k * OUT_CH + t], a);
        out[(size_t)n * OUT_CH + t] = a;
    }
}

// ---------------- launch ----------------
static void run_gemm(int c_sel, const float* bias, int M, int N_tot, int K_pad, int act) {
    dim3 g(N_tot / 128, (M + 127) / 128);
    k_mma<<<g, 256, SMEM_MMA>>>(c_sel, bias, M, N_tot, K_pad, act);
}

extern "C" void kernel_launch(void* const* d_in, const int* in_sizes, int n_in,
                              void* d_out, int out_size) {
    static const int MAP_INSERT[22] =
        {0,1,2,3,4,5,6,7,8,9,10,11,12,13,14,15,16,17,18,19,20,21};
    static const int MAP_ALPHA[22] =
        {21, 16, 4, 2, 5, 3, 0, 1, 18, 17,
         10, 8, 11, 9, 6, 7, 20, 19, 14, 12, 15, 13};
    const int* map = MAP_INSERT;
    if (n_in >= 22 && in_sizes[0] != N_NODES * IN_CH && in_sizes[21] == N_NODES * IN_CH)
        map = MAP_ALPHA;

    const float* x       = (const float*)d_in[map[0]];
    const void*  ei      = d_in[map[1]];
    const float* c1_wl   = (const float*)d_in[map[2]];
    const float* c1_bl   = (const float*)d_in[map[3]];
    const float* c1_wr   = (const float*)d_in[map[4]];
    const float* c1_br   = (const float*)d_in[map[5]];
    const float* c1_att  = (const float*)d_in[map[6]];
    const float* c1_bias = (const float*)d_in[map[7]];
    const float* ln1_w   = (const float*)d_in[map[8]];
    const float* ln1_b   = (const float*)d_in[map[9]];
    const float* c2_wl   = (const float*)d_in[map[10]];
    const float* c2_bl   = (const float*)d_in[map[11]];
    const float* c2_wr   = (const float*)d_in[map[12]];
    const float* c2_br   = (const float*)d_in[map[13]];
    const float* c2_att  = (const float*)d_in[map[14]];
    const float* c2_bias = (const float*)d_in[map[15]];
    const float* ln2_w   = (const float*)d_in[map[16]];
    const float* ln2_b   = (const float*)d_in[map[17]];
    const float* cls_w1  = (const float*)d_in[map[18]];
    const float* cls_b1  = (const float*)d_in[map[19]];
    const float* cls_w2  = (const float*)d_in[map[20]];
    const float* cls_b2  = (const float*)d_in[map[21]];
    float* out = (float*)d_out;

    cudaFuncSetAttribute(k_mma, cudaFuncAttributeMaxDynamicSharedMemorySize, SMEM_MMA);

    // CSR build
    k_detect<<<1, 1>>>((const unsigned long long*)ei);
    k_zero_csr<<<(N_NODES + 255) / 256, 256>>>();
    k_build<<<(E_TOT + 255) / 256, 256>>>(ei);
    k_scan<<<1, 1024>>>();
    k_scatter<<<(E_TOT + 255) / 256, 256>>>();

    int eb  = (E_TOT + 7) / 8;
    int e4b = (E_TOT * 4 + 255) / 256;
    int zb  = (N_NODES * 4 + 255) / 256;
    const int CB = 256;
    size_t a1_tot = (size_t)M_PAD * KP1, a2_tot = (size_t)M_PAD * KP2;
    size_t b1_tot = (size_t)HC * KP1,    b2_tot = (size_t)HC * KP2;

    // ---- conv1 (K = 1030 -> pad 1088) ----
    k_cvt_a<<<(int)((a1_tot + CB - 1) / CB), CB>>>(x, 0, N_NODES, IN_CH, KP1, M_PAD);
    k_cvt_b<<<(int)((b1_tot + CB - 1) / CB), CB>>>(c1_wl, IN_CH, HC, KP1);
    run_gemm(0, c1_bl, N_NODES, HC, KP1, 0);
    k_cvt_b<<<(int)((b1_tot + CB - 1) / CB), CB>>>(c1_wr, IN_CH, HC, KP1);
    run_gemm(1, c1_br, N_NODES, HC, KP1, 0);
    k_edge_scores<<<eb, 256>>>(c1_att);
    k_zero_soft<<<zb, 256>>>();
    k_edge_max<<<e4b, 256>>>();
    k_edge_exp<<<e4b, 256>>>();
    k_aggregate<<<N_NODES, 256>>>(c1_bias);
    k_ln_elu<<<N_NODES, 256>>>(ln1_w, ln1_b);

    // ---- conv2 (K = 1024) ----
    k_cvt_a<<<(int)((a2_tot + CB - 1) / CB), CB>>>(nullptr, 1, N_NODES, HC, KP2, M_PAD);
    k_cvt_b<<<(int)((b2_tot + CB - 1) / CB), CB>>>(c2_wl, HC, HC, KP2);
    run_gemm(0, c2_bl, N_NODES, HC, KP2, 0);
    k_cvt_b<<<(int)((b2_tot + CB - 1) / CB), CB>>>(c2_wr, HC, HC, KP2);
    run_gemm(1, c2_br, N_NODES, HC, KP2, 0);
    k_edge_scores<<<eb, 256>>>(c2_att);
    k_zero_soft<<<zb, 256>>>();
    k_edge_max<<<e4b, 256>>>();
    k_edge_exp<<<e4b, 256>>>();
    k_aggregate<<<N_NODES, 256>>>(c2_bias);
    k_ln_elu<<<N_NODES, 256>>>(ln2_w, ln2_b);

    // ---- classifier ----
    k_cvt_a<<<(int)((a2_tot + CB - 1) / CB), CB>>>(nullptr, 1, N_NODES, HC, KP2, M_PAD);
    k_cvt_b<<<(int)(((size_t)HID * KP2 + CB - 1) / CB), CB>>>(cls_w1, HC, HID, KP2);
    run_gemm(3, cls_b1, N_NODES, HID, KP2, 1);
    k_cls2<<<N_NODES, 64>>>(cls_w2, cls_b2, out);
}

// round 7
// speedup vs baseline: 2.5380x; 1.0432x over previous
#include <cuda_runtime.h>
#include <cuda_bf16.h>
#include <math.h>
#include <stdint.h>

#define N_NODES 10000
#define N_EDGES 160000
#define E_TOT   170000
#define IN_CH   1030
#define HC      1024
#define HID     256
#define OUT_CH  49
#define M_PAD   10112          // 79 * 128
#define KP1     1088           // conv1 K padded
#define KP2     1024           // conv2/cls1 K

// ---------------- device scratch ----------------
__device__ float g_xl[(size_t)N_NODES * HC];
__device__ float g_xr[(size_t)N_NODES * HC];
__device__ float g_cls[(size_t)N_NODES * HID];
__device__ __align__(128) __nv_bfloat16 g_ahi[(size_t)M_PAD * KP1];
__device__ __align__(128) __nv_bfloat16 g_alo[(size_t)M_PAD * KP1];
__device__ __align__(128) __nv_bfloat16 g_bhi[(size_t)HC * KP1];
__device__ __align__(128) __nv_bfloat16 g_blo[(size_t)HC * KP1];
__device__ int      g_src[E_TOT];
__device__ int      g_dst[E_TOT];
__device__ float    g_esc[E_TOT * 4];
__device__ unsigned g_emax[N_NODES * 4];
__device__ float    g_den [N_NODES * 4];
__device__ int g_cnt[N_NODES];
__device__ int g_rowptr[N_NODES + 1];
__device__ int g_cursor[N_NODES];
__device__ int g_perm[E_TOT];
__device__ int g_ei_is64;

__device__ __forceinline__ unsigned f2u(float f) {
    unsigned u = __float_as_uint(f);
    return (u & 0x80000000u) ? ~u : (u | 0x80000000u);
}
__device__ __forceinline__ float u2f(unsigned u) {
    return (u & 0x80000000u) ? __uint_as_float(u & 0x7fffffffu) : __uint_as_float(~u);
}

// ---------------- asm helpers ----------------
__device__ __forceinline__ uint32_t smem_u32(const void* p) {
    uint32_t a;
    asm("{ .reg .u64 t; cvta.to.shared.u64 t, %1; cvt.u32.u64 %0, t; }" : "=r"(a) : "l"(p));
    return a;
}
__device__ __forceinline__ void cp_async16(uint32_t dst, const void* src) {
    asm volatile("cp.async.cg.shared.global [%0], [%1], 16;" :: "r"(dst), "l"(src));
}
#define CP_COMMIT() asm volatile("cp.async.commit_group;")
#define CP_WAIT0()  asm volatile("cp.async.wait_group 0;" ::: "memory")
#define CP_WAIT1()  asm volatile("cp.async.wait_group 1;" ::: "memory")

__device__ __forceinline__ void ldsm4(uint32_t* r, uint32_t addr) {
    asm volatile("ldmatrix.sync.aligned.m8n8.x4.shared.b16 {%0,%1,%2,%3}, [%4];"
        : "=r"(r[0]), "=r"(r[1]), "=r"(r[2]), "=r"(r[3]) : "r"(addr));
}
__device__ __forceinline__ void mma16816(float* c, const uint32_t* a,
                                         uint32_t b0, uint32_t b1) {
    asm volatile(
        "mma.sync.aligned.m16n8k16.row.col.f32.bf16.bf16.f32 "
        "{%0,%1,%2,%3}, {%4,%5,%6,%7}, {%8,%9}, {%0,%1,%2,%3};"
        : "+f"(c[0]), "+f"(c[1]), "+f"(c[2]), "+f"(c[3])
        : "r"(a[0]), "r"(a[1]), "r"(a[2]), "r"(a[3]), "r"(b0), "r"(b1));
}

// ---------------- fp32 -> split bf16 conversion ----------------
__global__ void k_cvt_a(const float* __restrict__ A, int M_real, int K_real,
                        int K_pad, int M_use) {
    size_t idx = (size_t)blockIdx.x * blockDim.x + threadIdx.x;
    size_t tot = (size_t)M_use * K_pad;
    if (idx >= tot) return;
    int r = (int)(idx / K_pad), c = (int)(idx % K_pad);
    float x = (r < M_real && c < K_real) ? A[(size_t)r * K_real + c] : 0.f;
    __nv_bfloat16 hi = __float2bfloat16_rn(x);
    __nv_bfloat16 lo = __float2bfloat16_rn(x - __bfloat162float(hi));
    g_ahi[idx] = hi;
    g_alo[idx] = lo;
}

__global__ void k_cvt_b(const float* __restrict__ B, int K_real, int N, int K_pad) {
    size_t idx = (size_t)blockIdx.x * blockDim.x + threadIdx.x;
    size_t tot = (size_t)N * K_pad;
    if (idx >= tot) return;
    int n = (int)(idx / K_pad), k = (int)(idx % K_pad);
    float x = (k < K_real) ? B[(size_t)k * N + n] : 0.f;
    __nv_bfloat16 hi = __float2bfloat16_rn(x);
    __nv_bfloat16 lo = __float2bfloat16_rn(x - __bfloat162float(hi));
    g_bhi[idx] = hi;
    g_blo[idx] = lo;
}

// ---------------- mma.sync split-bf16 GEMM, ldmatrix + 3-stage pipeline -----
#define ROWB   80
#define TIL    (128 * ROWB)     // 10240
#define STG    (4 * TIL)        // 40960
#define NSTAGE 3
#define SMEM_MMA (NSTAGE * STG)

__device__ __forceinline__ void load_stage(uint32_t sb, int it, int tid,
                                           const __nv_bfloat16* s0, const __nv_bfloat16* s1,
                                           const __nv_bfloat16* s2, const __nv_bfloat16* s3,
                                           int K_pad) {
    uint32_t stage = sb + (uint32_t)(it % NSTAGE) * STG;
    int k0 = it * 32;
    const __nv_bfloat16* srcs[4] = {s0, s1, s2, s3};
    #pragma unroll
    for (int q = 0; q < 8; q++) {
        int id = tid + q * 256;            // 4 tiles x 128 rows x 4 x 16B
        int t = id >> 9, r = (id >> 2) & 127, u = id & 3;
        cp_async16(stage + t * TIL + r * ROWB + u * 16,
                   srcs[t] + (size_t)r * K_pad + k0 + u * 8);
    }
    CP_COMMIT();
}

__global__ __launch_bounds__(256)
void k_mma(int c_sel, const float* __restrict__ bias,
           int M, int N_tot, int K_pad, int act) {
    extern __shared__ char sm[];
    float* C = (c_sel == 0) ? g_xl : (c_sel == 1) ? g_xr : g_cls;

    int tid = threadIdx.x, w = tid >> 5, l = tid & 31;
    int wm = w >> 1, wn = w & 1;                 // warp grid 4 x 2
    int bm = blockIdx.y * 128, bn = blockIdx.x * 128;
    uint32_t sb = smem_u32(sm);
    int q = l >> 3;

    // ldmatrix per-thread row-pointer offsets (within a tile)
    uint32_t aoff = (uint32_t)((wm * 32 + ((q & 1) << 3) + (l & 7)) * ROWB + ((q >> 1) << 4));
    uint32_t boff = (uint32_t)((wn * 64 + ((q >> 1) << 3) + (l & 7)) * ROWB + ((q & 1) << 4));

    const __nv_bfloat16* sA_hi = g_ahi + (size_t)bm * K_pad;
    const __nv_bfloat16* sA_lo = g_alo + (size_t)bm * K_pad;
    const __nv_bfloat16* sB_hi = g_bhi + (size_t)bn * K_pad;
    const __nv_bfloat16* sB_lo = g_blo + (size_t)bn * K_pad;

    float acc[2][8][4];
    #pragma unroll
    for (int m = 0; m < 2; m++)
        #pragma unroll
        for (int n = 0; n < 8; n++)
            #pragma unroll
            for (int i = 0; i < 4; i++) acc[m][n][i] = 0.f;

    int nk = K_pad / 32;
    load_stage(sb, 0, tid, sA_hi, sA_lo, sB_hi, sB_lo, K_pad);
    load_stage(sb, 1, tid, sA_hi, sA_lo, sB_hi, sB_lo, K_pad);

    for (int it = 0; it < nk; it++) {
        if (it == nk - 1) { CP_WAIT0(); } else { CP_WAIT1(); }
        __syncthreads();
        if (it + 2 < nk) load_stage(sb, it + 2, tid, sA_hi, sA_lo, sB_hi, sB_lo, K_pad);

        uint32_t stage = sb + (uint32_t)(it % NSTAGE) * STG;
        // 3 passes: (A_hi,B_hi), (A_hi,B_lo), (A_lo,B_hi)
        #pragma unroll
        for (int pass = 0; pass < 3; pass++) {
            uint32_t pA = stage + ((pass < 2) ? 0u : (uint32_t)TIL);
            uint32_t pB = stage + ((pass == 1) ? 3u * TIL : 2u * TIL);
            #pragma unroll
            for (int kc = 0; kc < 2; kc++) {
                uint32_t a[2][4], b[4][4];
                ldsm4(a[0], pA + aoff + kc * 32);
                ldsm4(a[1], pA + aoff + 16 * ROWB + kc * 32);
                #pragma unroll
                for (int p = 0; p < 4; p++)
                    ldsm4(b[p], pB + boff + p * (16 * ROWB) + kc * 32);
                #pragma unroll
                for (int n = 0; n < 8; n++) {
                    uint32_t b0 = b[n >> 1][(n & 1) * 2];
                    uint32_t b1 = b[n >> 1][(n & 1) * 2 + 1];
                    mma16816(acc[0][n], a[0], b0, b1);
                    mma16816(acc[1][n], a[1], b0, b1);
                }
            }
        }
    }

    // epilogue
    #pragma unroll
    for (int m = 0; m < 2; m++) {
        #pragma unroll
        for (int n = 0; n < 8; n++) {
            int col = bn + wn * 64 + n * 8 + (l & 3) * 2;
            float2 bv = *(const float2*)(bias + col);
            int r0 = bm + wm * 32 + m * 16 + (l >> 2);
            #pragma unroll
            for (int hh = 0; hh < 2; hh++) {
                int row = r0 + hh * 8;
                if (row < M) {
                    float vx = acc[m][n][hh * 2    ] + bv.x;
                    float vy = acc[m][n][hh * 2 + 1] + bv.y;
                    if (act == 1) {
                        vx = vx > 0.f ? vx : expm1f(vx);
                        vy = vy > 0.f ? vy : expm1f(vy);
                    }
                    *(float2*)(C + (size_t)row * N_tot + col) = make_float2(vx, vy);
                }
            }
        }
    }
}

// ---------------- edge_index dtype detection ----------------
__global__ void k_detect(const unsigned long long* __restrict__ ei64) {
    int is64 = 1;
    for (int i = 0; i < 64; i++)
        if (ei64[i] >= (1ULL << 32)) { is64 = 0; break; }
    g_ei_is64 = is64;
}

// ---------------- CSR build ----------------
__global__ void k_zero_csr() {
    int i = blockIdx.x * blockDim.x + threadIdx.x;
    if (i < N_NODES) g_cnt[i] = 0;
}

__global__ void k_build(const void* __restrict__ ei) {
    int i = blockIdx.x * blockDim.x + threadIdx.x;
    if (i >= E_TOT) return;
    int s, d;
    if (i < N_EDGES) {
        if (g_ei_is64) {
            const long long* p = (const long long*)ei;
            s = (int)p[i]; d = (int)p[N_EDGES + i];
        } else {
            const int* p = (const int*)ei;
            s = p[i]; d = p[N_EDGES + i];
        }
    } else {
        s = d = i - N_EDGES;
    }
    if ((unsigned)s >= N_NODES) s = 0;
    if ((unsigned)d >= N_NODES) d = 0;
    g_src[i] = s;
    g_dst[i] = d;
    atomicAdd(&g_cnt[d], 1);
}

__global__ void k_scan() {
    __shared__ int wsum[32];
    __shared__ int carry_s;
    int tid = threadIdx.x;
    if (tid == 0) carry_s = 0;
    __syncthreads();
    for (int base = 0; base < N_NODES; base += 1024) {
        int i = base + tid;
        int v = (i < N_NODES) ? g_cnt[i] : 0;
        int incl = v;
        int lane = tid & 31, wid = tid >> 5;
        #pragma unroll
        for (int o = 1; o < 32; o <<= 1) {
            int t = __shfl_up_sync(0xffffffffu, incl, o);
            if (lane >= o) incl += t;
        }
        if (lane == 31) wsum[wid] = incl;
        __syncthreads();
        if (wid == 0) {
            int s = wsum[lane];
            #pragma unroll
            for (int o = 1; o < 32; o <<= 1) {
                int t = __shfl_up_sync(0xffffffffu, s, o);
                if (lane >= o) s += t;
            }
            wsum[lane] = s;
        }
        __syncthreads();
        int off = (wid > 0) ? wsum[wid - 1] : 0;
        int excl = carry_s + off + incl - v;
        if (i < N_NODES) { g_rowptr[i] = excl; g_cursor[i] = excl; }
        __syncthreads();
        if (tid == 0) carry_s += wsum[31];
        __syncthreads();
    }
    if (tid == 0) g_rowptr[N_NODES] = carry_s;
}

__global__ void k_scatter() {
    int e = blockIdx.x * blockDim.x + threadIdx.x;
    if (e >= E_TOT) return;
    int pos = atomicAdd(&g_cursor[g_dst[e]], 1);
    g_perm[pos] = e;
}

// ---------------- edge attention scores (float4 vectorized) ----------------
__global__ void k_edge_scores(const float* __restrict__ att) {
    int e = (blockIdx.x * blockDim.x + threadIdx.x) >> 5;
    int lane = threadIdx.x & 31;
    if (e >= E_TOT) return;
    const float4* pl = (const float4*)(g_xl + (size_t)g_src[e] * HC);
    const float4* pr = (const float4*)(g_xr + (size_t)g_dst[e] * HC);
    const float4* pa = (const float4*)att;
    float acc[4] = {0.f, 0.f, 0.f, 0.f};
    #pragma unroll
    for (int i = 0; i < 8; i++) {
        int idx = i * 32 + lane;           // float4 index; head = i/2 (uniform)
        float4 a = pl[idx], b = pr[idx], t = pa[idx];
        float mx = a.x + b.x, my = a.y + b.y, mz = a.z + b.z, mw = a.w + b.w;
        mx = mx > 0.f ? mx : 0.2f * mx;
        my = my > 0.f ? my : 0.2f * my;
        mz = mz > 0.f ? mz : 0.2f * mz;
        mw = mw > 0.f ? mw : 0.2f * mw;
        acc[i >> 1] += mx * t.x + my * t.y + mz * t.z + mw * t.w;
    }
    #pragma unroll
    for (int h = 0; h < 4; h++) {
        float v = acc[h];
        #pragma unroll
        for (int o = 16; o; o >>= 1) v += __shfl_xor_sync(0xffffffffu, v, o);
        if (lane == 0) g_esc[e * 4 + h] = v;
    }
}

__global__ void k_zero_soft() {
    int i = blockIdx.x * blockDim.x + threadIdx.x;
    if (i < N_NODES * 4) { g_emax[i] = 0u; g_den[i] = 0.f; }
}

__global__ void k_edge_max() {
    int i = blockIdx.x * blockDim.x + threadIdx.x;
    if (i >= E_TOT * 4) return;
    int e = i >> 2, h = i & 3;
    atomicMax(&g_emax[g_dst[e] * 4 + h], f2u(g_esc[i]));
}

__global__ void k_edge_exp() {
    int i = blockIdx.x * blockDim.x + threadIdx.x;
    if (i >= E_TOT * 4) return;
    int e = i >> 2, h = i & 3;
    int d = g_dst[e];
    float p = expf(g_esc[i] - u2f(g_emax[d * 4 + h]));
    g_esc[i] = p;
    atomicAdd(&g_den[d * 4 + h], p);
}

// ---- fused aggregation + LayerNorm + ELU + split-bf16 write (A for next GEMM)
__global__ __launch_bounds__(256)
void k_agg_ln(const float* __restrict__ bias,
              const float* __restrict__ w, const float* __restrict__ b) {
    int n = blockIdx.x;
    int tid = threadIdx.x;
    float inv[4];
    #pragma unroll
    for (int h = 0; h < 4; h++) inv[h] = 1.f / (g_den[n * 4 + h] + 1e-16f);
    float acc[4] = {0.f, 0.f, 0.f, 0.f};
    int beg = g_rowptr[n], end = g_rowptr[n + 1];
    for (int j = beg; j < end; j++) {
        int e = g_perm[j];
        int s = g_src[e];
        float4 p = *(const float4*)&g_esc[e * 4];
        const float* row = g_xl + (size_t)s * HC;
        acc[0] = fmaf(p.x, row[tid      ], acc[0]);
        acc[1] = fmaf(p.y, row[tid + 256], acc[1]);
        acc[2] = fmaf(p.z, row[tid + 512], acc[2]);
        acc[3] = fmaf(p.w, row[tid + 768], acc[3]);
    }
    float v[4];
    float s = 0.f, s2 = 0.f;
    #pragma unroll
    for (int i = 0; i < 4; i++) {
        v[i] = acc[i] * inv[i] + bias[tid + i * 256];
        s += v[i];
        s2 += v[i] * v[i];
    }
    __shared__ float rs[8], rs2[8];
    int lane = tid & 31, wid = tid >> 5;
    #pragma unroll
    for (int o = 16; o; o >>= 1) {
        s  += __shfl_xor_sync(0xffffffffu, s,  o);
        s2 += __shfl_xor_sync(0xffffffffu, s2, o);
    }
    if (lane == 0) { rs[wid] = s; rs2[wid] = s2; }
    __syncthreads();
    if (tid == 0) {
        float a = 0.f, a2 = 0.f;
        #pragma unroll
        for (int i = 0; i < 8; i++) { a += rs[i]; a2 += rs2[i]; }
        rs[0] = a; rs2[0] = a2;
    }
    __syncthreads();
    float mu = rs[0] * (1.f / HC);
    float var = rs2[0] * (1.f / HC) - mu * mu;
    float r = rsqrtf(var + 1e-5f);
    size_t base = (size_t)n * KP2;
    #pragma unroll
    for (int i = 0; i < 4; i++) {
        int c = tid + i * 256;
        float y = (v[i] - mu) * r * w[c] + b[c];
        y = y > 0.f ? y : expm1f(y);
        __nv_bfloat16 hi = __float2bfloat16_rn(y);
        __nv_bfloat16 lo = __float2bfloat16_rn(y - __bfloat162float(hi));
        g_ahi[base + c] = hi;
        g_alo[base + c] = lo;
    }
}

// ---------------- classifier layer 2 ----------------
__global__ void k_cls2(const float* __restrict__ w2, const float* __restrict__ b2,
                       float* __restrict__ out) {
    __shared__ float sh[HID];
    int n = blockIdx.x;
    for (int i = threadIdx.x; i < HID; i += 64) sh[i] = g_cls[(size_t)n * HID + i];
    __syncthreads();
    int t = threadIdx.x;
    if (t < OUT_CH) {
        float a = b2[t];
        for (int k = 0; k < HID; k++) a = fmaf(sh[k], w2[k * OUT_CH + t], a);
        out[(size_t)n * OUT_CH + t] = a;
    }
}

// ---------------- launch ----------------
static void run_gemm(int c_sel, const float* bias, int M, int N_tot, int K_pad, int act) {
    dim3 g(N_tot / 128, (M + 127) / 128);
    k_mma<<<g, 256, SMEM_MMA>>>(c_sel, bias, M, N_tot, K_pad, act);
}

extern "C" void kernel_launch(void* const* d_in, const int* in_sizes, int n_in,
                              void* d_out, int out_size) {
    static const int MAP_INSERT[22] =
        {0,1,2,3,4,5,6,7,8,9,10,11,12,13,14,15,16,17,18,19,20,21};
    static const int MAP_ALPHA[22] =
        {21, 16, 4, 2, 5, 3, 0, 1, 18, 17,
         10, 8, 11, 9, 6, 7, 20, 19, 14, 12, 15, 13};
    const int* map = MAP_INSERT;
    if (n_in >= 22 && in_sizes[0] != N_NODES * IN_CH && in_sizes[21] == N_NODES * IN_CH)
        map = MAP_ALPHA;

    const float* x       = (const float*)d_in[map[0]];
    const void*  ei      = d_in[map[1]];
    const float* c1_wl   = (const float*)d_in[map[2]];
    const float* c1_bl   = (const float*)d_in[map[3]];
    const float* c1_wr   = (const float*)d_in[map[4]];
    const float* c1_br   = (const float*)d_in[map[5]];
    const float* c1_att  = (const float*)d_in[map[6]];
    const float* c1_bias = (const float*)d_in[map[7]];
    const float* ln1_w   = (const float*)d_in[map[8]];
    const float* ln1_b   = (const float*)d_in[map[9]];
    const float* c2_wl   = (const float*)d_in[map[10]];
    const float* c2_bl   = (const float*)d_in[map[11]];
    const float* c2_wr   = (const float*)d_in[map[12]];
    const float* c2_br   = (const float*)d_in[map[13]];
    const float* c2_att  = (const float*)d_in[map[14]];
    const float* c2_bias = (const float*)d_in[map[15]];
    const float* ln2_w   = (const float*)d_in[map[16]];
    const float* ln2_b   = (const float*)d_in[map[17]];
    const float* cls_w1  = (const float*)d_in[map[18]];
    const float* cls_b1  = (const float*)d_in[map[19]];
    const float* cls_w2  = (const float*)d_in[map[20]];
    const float* cls_b2  = (const float*)d_in[map[21]];
    float* out = (float*)d_out;

    cudaFuncSetAttribute(k_mma, cudaFuncAttributeMaxDynamicSharedMemorySize, SMEM_MMA);

    // CSR build
    k_detect<<<1, 1>>>((const unsigned long long*)ei);
    k_zero_csr<<<(N_NODES + 255) / 256, 256>>>();
    k_build<<<(E_TOT + 255) / 256, 256>>>(ei);
    k_scan<<<1, 1024>>>();
    k_scatter<<<(E_TOT + 255) / 256, 256>>>();

    int eb  = (E_TOT + 7) / 8;
    int e4b = (E_TOT * 4 + 255) / 256;
    int zb  = (N_NODES * 4 + 255) / 256;
    const int CB = 256;
    size_t a1_tot = (size_t)M_PAD * KP1;
    size_t b1_tot = (size_t)HC * KP1, b2_tot = (size_t)HC * KP2;

    // ---- conv1 (K = 1030 -> pad 1088) ----
    k_cvt_a<<<(int)((a1_tot + CB - 1) / CB), CB>>>(x, N_NODES, IN_CH, KP1, M_PAD);
    k_cvt_b<<<(int)((b1_tot + CB - 1) / CB), CB>>>(c1_wl, IN_CH, HC, KP1);
    run_gemm(0, c1_bl, N_NODES, HC, KP1, 0);
    k_cvt_b<<<(int)((b1_tot + CB - 1) / CB), CB>>>(c1_wr, IN_CH, HC, KP1);
    run_gemm(1, c1_br, N_NODES, HC, KP1, 0);
    k_edge_scores<<<eb, 256>>>(c1_att);
    k_zero_soft<<<zb, 256>>>();
    k_edge_max<<<e4b, 256>>>();
    k_edge_exp<<<e4b, 256>>>();
    k_agg_ln<<<N_NODES, 256>>>(c1_bias, ln1_w, ln1_b);   // writes g_ahi/g_alo (K=1024)

    // ---- conv2 (K = 1024) ----
    k_cvt_b<<<(int)((b2_tot + CB - 1) / CB), CB>>>(c2_wl, HC, HC, KP2);
    run_gemm(0, c2_bl, N_NODES, HC, KP2, 0);
    k_cvt_b<<<(int)((b2_tot + CB - 1) / CB), CB>>>(c2_wr, HC, HC, KP2);
    run_gemm(1, c2_br, N_NODES, HC, KP2, 0);
    k_edge_scores<<<eb, 256>>>(c2_att);
    k_zero_soft<<<zb, 256>>>();
    k_edge_max<<<e4b, 256>>>();
    k_edge_exp<<<e4b, 256>>>();
    k_agg_ln<<<N_NODES, 256>>>(c2_bias, ln2_w, ln2_b);   // writes g_ahi/g_alo (K=1024)

    // ---- classifier ----
    k_cvt_b<<<(int)(((size_t)HID * KP2 + CB - 1) / CB), CB>>>(cls_w1, HC, HID, KP2);
    run_gemm(2, cls_b1, N_NODES, HID, KP2, 1);           // c_sel=2 -> g_cls, ELU
    k_cls2<<<N_NODES, 64>>>(cls_w2, cls_b2, out);
}

// round 10
// speedup vs baseline: 2.6457x; 1.0425x over previous
#include <cuda_runtime.h>
#include <cuda_bf16.h>
#include <math.h>
#include <stdint.h>

#define N_NODES 10000
#define N_EDGES 160000
#define E_TOT   170000
#define IN_CH   1030
#define HC      1024
#define HID     256
#define OUT_CH  49
#define M_PAD   10112          // 79 * 128
#define KP1     1088           // conv1 K padded
#define KP2     1024           // conv2/cls1 K

// ---------------- device scratch ----------------
__device__ float g_xl[(size_t)N_NODES * HC];
__device__ float g_xr[(size_t)N_NODES * HC];
__device__ float g_cls[(size_t)N_NODES * HID];
__device__ float g_bias2[2 * HC];
__device__ __align__(128) __nv_bfloat16 g_ahi[(size_t)M_PAD * KP1];
__device__ __align__(128) __nv_bfloat16 g_alo[(size_t)M_PAD * KP1];
__device__ __align__(128) __nv_bfloat16 g_bhi[(size_t)2 * HC * KP1];
__device__ __align__(128) __nv_bfloat16 g_blo[(size_t)2 * HC * KP1];
__device__ int      g_src[E_TOT];
__device__ int      g_dst[E_TOT];
__device__ float    g_esc[E_TOT * 4];
__device__ unsigned g_emax[N_NODES * 4];
__device__ float    g_den [N_NODES * 4];
__device__ int g_cnt[N_NODES];
__device__ int g_rowptr[N_NODES + 1];
__device__ int g_cursor[N_NODES];
__device__ int g_perm[E_TOT];
__device__ int g_ei_is64;

__device__ __forceinline__ unsigned f2u(float f) {
    unsigned u = __float_as_uint(f);
    return (u & 0x80000000u) ? ~u : (u | 0x80000000u);
}
__device__ __forceinline__ float u2f(unsigned u) {
    return (u & 0x80000000u) ? __uint_as_float(u & 0x7fffffffu) : __uint_as_float(~u);
}

// ---------------- asm helpers ----------------
__device__ __forceinline__ uint32_t smem_u32(const void* p) {
    uint32_t a;
    asm("{ .reg .u64 t; cvta.to.shared.u64 t, %1; cvt.u32.u64 %0, t; }" : "=r"(a) : "l"(p));
    return a;
}
__device__ __forceinline__ void cp_async16(uint32_t dst, const void* src) {
    asm volatile("cp.async.cg.shared.global [%0], [%1], 16;" :: "r"(dst), "l"(src));
}
#define CP_COMMIT() asm volatile("cp.async.commit_group;")
#define CP_WAIT0()  asm volatile("cp.async.wait_group 0;" ::: "memory")
#define CP_WAIT1()  asm volatile("cp.async.wait_group 1;" ::: "memory")

__device__ __forceinline__ void ldsm4(uint32_t* r, uint32_t addr) {
    asm volatile("ldmatrix.sync.aligned.m8n8.x4.shared.b16 {%0,%1,%2,%3}, [%4];"
        : "=r"(r[0]), "=r"(r[1]), "=r"(r[2]), "=r"(r[3]) : "r"(addr));
}
__device__ __forceinline__ void mma16816(float* c, const uint32_t* a,
                                         uint32_t b0, uint32_t b1) {
    asm volatile(
        "mma.sync.aligned.m16n8k16.row.col.f32.bf16.bf16.f32 "
        "{%0,%1,%2,%3}, {%4,%5,%6,%7}, {%8,%9}, {%0,%1,%2,%3};"
        : "+f"(c[0]), "+f"(c[1]), "+f"(c[2]), "+f"(c[3])
        : "r"(a[0]), "r"(a[1]), "r"(a[2]), "r"(a[3]), "r"(b0), "r"(b1));
}

// ---------------- conversions ----------------
__global__ void k_cvt_a(const float* __restrict__ A, int M_real, int K_real,
                        int K_pad, int M_use) {
    size_t idx = (size_t)blockIdx.x * blockDim.x + threadIdx.x;
    size_t tot = (size_t)M_use * K_pad;
    if (idx >= tot) return;
    int r = (int)(idx / K_pad), c = (int)(idx % K_pad);
    float x = (r < M_real && c < K_real) ? A[(size_t)r * K_real + c] : 0.f;
    __nv_bfloat16 hi = __float2bfloat16_rn(x);
    __nv_bfloat16 lo = __float2bfloat16_rn(x - __bfloat162float(hi));
    g_ahi[idx] = hi;
    g_alo[idx] = lo;
}

// two [K_real,1024] weights -> one [2048, K_pad] transposed split-bf16 buffer
__global__ void k_cvt_b2(const float* __restrict__ Bl, const float* __restrict__ Br,
                         int K_real, int K_pad) {
    size_t idx = (size_t)blockIdx.x * blockDim.x + threadIdx.x;
    size_t tot = (size_t)2 * HC * K_pad;
    if (idx >= tot) return;
    int n = (int)(idx / K_pad), k = (int)(idx % K_pad);
    const float* B = (n < HC) ? Bl : Br;
    int nn = (n < HC) ? n : n - HC;
    float x = (k < K_real) ? B[(size_t)k * HC + nn] : 0.f;
    __nv_bfloat16 hi = __float2bfloat16_rn(x);
    __nv_bfloat16 lo = __float2bfloat16_rn(x - __bfloat162float(hi));
    g_bhi[idx] = hi;
    g_blo[idx] = lo;
}

// single weight [K_real, N] -> [N, K_pad]
__global__ void k_cvt_b(const float* __restrict__ B, int K_real, int N, int K_pad) {
    size_t idx = (size_t)blockIdx.x * blockDim.x + threadIdx.x;
    size_t tot = (size_t)N * K_pad;
    if (idx >= tot) return;
    int n = (int)(idx / K_pad), k = (int)(idx % K_pad);
    float x = (k < K_real) ? B[(size_t)k * N + n] : 0.f;
    __nv_bfloat16 hi = __float2bfloat16_rn(x);
    __nv_bfloat16 lo = __float2bfloat16_rn(x - __bfloat162float(hi));
    g_bhi[idx] = hi;
    g_blo[idx] = lo;
}

__global__ void k_pack_bias(const float* __restrict__ bl, const float* __restrict__ br) {
    int i = blockIdx.x * blockDim.x + threadIdx.x;
    if (i < HC) g_bias2[i] = bl[i];
    else if (i < 2 * HC) g_bias2[i] = br[i - HC];
}

// ---------------- mma.sync split-bf16 GEMM (ldmatrix, 2-stage, 2 CTA/SM) ----
#define ROWB   80
#define TIL    (128 * ROWB)     // 10240
#define STG    (4 * TIL)        // 40960
#define SMEM_MMA (2 * STG)      // 80KB -> 2 CTAs/SM

__device__ __forceinline__ void load_stage(uint32_t sb, int it, int tid,
                                           const __nv_bfloat16* s0, const __nv_bfloat16* s1,
                                           const __nv_bfloat16* s2, const __nv_bfloat16* s3,
                                           int K_pad) {
    uint32_t stage = sb + (uint32_t)(it & 1) * STG;
    int k0 = it * 32;
    const __nv_bfloat16* srcs[4] = {s0, s1, s2, s3};
    #pragma unroll
    for (int q = 0; q < 8; q++) {
        int id = tid + q * 256;
        int t = id >> 9, r = (id >> 2) & 127, u = id & 3;
        cp_async16(stage + t * TIL + r * ROWB + u * 16,
                   srcs[t] + (size_t)r * K_pad + k0 + u * 8);
    }
    CP_COMMIT();
}

// c_sel: 2 = g_cls (bias param, act), 3 = split g_xl/g_xr (g_bias2)
__global__ __launch_bounds__(256)
void k_mma(int c_sel, const float* __restrict__ bias,
           int M, int N_tot, int K_pad, int act) {
    extern __shared__ char sm[];
    int tid = threadIdx.x, w = tid >> 5, l = tid & 31;
    int wm = w >> 1, wn = w & 1;
    int bm = blockIdx.y * 128, bn = blockIdx.x * 128;
    uint32_t sb = smem_u32(sm);
    int q = l >> 3;

    uint32_t aoff = (uint32_t)((wm * 32 + ((q & 1) << 3) + (l & 7)) * ROWB + ((q >> 1) << 4));
    uint32_t boff = (uint32_t)((wn * 64 + ((q >> 1) << 3) + (l & 7)) * ROWB + ((q & 1) << 4));

    const __nv_bfloat16* sA_hi = g_ahi + (size_t)bm * K_pad;
    const __nv_bfloat16* sA_lo = g_alo + (size_t)bm * K_pad;
    const __nv_bfloat16* sB_hi = g_bhi + (size_t)bn * K_pad;
    const __nv_bfloat16* sB_lo = g_blo + (size_t)bn * K_pad;

    float acc[2][8][4];
    #pragma unroll
    for (int m = 0; m < 2; m++)
        #pragma unroll
        for (int n = 0; n < 8; n++)
            #pragma unroll
            for (int i = 0; i < 4; i++) acc[m][n][i] = 0.f;

    int nk = K_pad / 32;
    load_stage(sb, 0, tid, sA_hi, sA_lo, sB_hi, sB_lo, K_pad);
    load_stage(sb, 1, tid, sA_hi, sA_lo, sB_hi, sB_lo, K_pad);

    for (int it = 0; it < nk; it++) {
        if (it == nk - 1) { CP_WAIT0(); } else { CP_WAIT1(); }
        __syncthreads();
        uint32_t stage = sb + (uint32_t)(it & 1) * STG;
        #pragma unroll
        for (int pass = 0; pass < 3; pass++) {
            uint32_t pA = stage + ((pass < 2) ? 0u : (uint32_t)TIL);
            uint32_t pB = stage + ((pass == 1) ? 3u * TIL : 2u * TIL);
            #pragma unroll
            for (int kc = 0; kc < 2; kc++) {
                uint32_t a[2][4], b[4][4];
                ldsm4(a[0], pA + aoff + kc * 32);
                ldsm4(a[1], pA + aoff + 16 * ROWB + kc * 32);
                #pragma unroll
                for (int p = 0; p < 4; p++)
                    ldsm4(b[p], pB + boff + p * (16 * ROWB) + kc * 32);
                #pragma unroll
                for (int n = 0; n < 8; n++) {
                    uint32_t b0 = b[n >> 1][(n & 1) * 2];
                    uint32_t b1 = b[n >> 1][(n & 1) * 2 + 1];
                    mma16816(acc[0][n], a[0], b0, b1);
                    mma16816(acc[1][n], a[1], b0, b1);
                }
            }
        }
        __syncthreads();
        if (it + 2 < nk) load_stage(sb, it + 2, tid, sA_hi, sA_lo, sB_hi, sB_lo, K_pad);
    }

    // epilogue
    #pragma unroll
    for (int m = 0; m < 2; m++) {
        #pragma unroll
        for (int n = 0; n < 8; n++) {
            int cglob = bn + wn * 64 + n * 8 + (l & 3) * 2;
            float* Cp;
            int cc;
            float2 bv;
            if (c_sel == 3) {
                bool right = cglob >= HC;
                Cp = right ? g_xr : g_xl;
                cc = right ? cglob - HC : cglob;
                bv = *(const float2*)(g_bias2 + cglob);
            } else {
                Cp = g_cls;
                cc = cglob;
                bv = *(const float2*)(bias + cglob);
            }
            int stride = (c_sel == 3) ? HC : N_tot;
            int r0 = bm + wm * 32 + m * 16 + (l >> 2);
            #pragma unroll
            for (int hh = 0; hh < 2; hh++) {
                int row = r0 + hh * 8;
                if (row < M) {
                    float vx = acc[m][n][hh * 2    ] + bv.x;
                    float vy = acc[m][n][hh * 2 + 1] + bv.y;
                    if (act == 1) {
                        vx = vx > 0.f ? vx : expm1f(vx);
                        vy = vy > 0.f ? vy : expm1f(vy);
                    }
                    *(float2*)(Cp + (size_t)row * stride + cc) = make_float2(vx, vy);
                }
            }
        }
    }
}

// ---------------- edge_index dtype detection ----------------
__global__ void k_detect(const unsigned long long* __restrict__ ei64) {
    int is64 = 1;
    for (int i = 0; i < 64; i++)
        if (ei64[i] >= (1ULL << 32)) { is64 = 0; break; }
    g_ei_is64 = is64;
}

// ---------------- CSR build ----------------
__global__ void k_zero_csr() {
    int i = blockIdx.x * blockDim.x + threadIdx.x;
    if (i < N_NODES) g_cnt[i] = 0;
}

__global__ void k_build(const void* __restrict__ ei) {
    int i = blockIdx.x * blockDim.x + threadIdx.x;
    if (i >= E_TOT) return;
    int s, d;
    if (i < N_EDGES) {
        if (g_ei_is64) {
            const long long* p = (const long long*)ei;
            s = (int)p[i]; d = (int)p[N_EDGES + i];
        } else {
            const int* p = (const int*)ei;
            s = p[i]; d = p[N_EDGES + i];
        }
    } else {
        s = d = i - N_EDGES;
    }
    if ((unsigned)s >= N_NODES) s = 0;
    if ((unsigned)d >= N_NODES) d = 0;
    g_src[i] = s;
    g_dst[i] = d;
    atomicAdd(&g_cnt[d], 1);
}

__global__ void k_scan() {
    __shared__ int wsum[32];
    __shared__ int carry_s;
    int tid = threadIdx.x;
    if (tid == 0) carry_s = 0;
    __syncthreads();
    for (int base = 0; base < N_NODES; base += 1024) {
        int i = base + tid;
        int v = (i < N_NODES) ? g_cnt[i] : 0;
        int incl = v;
        int lane = tid & 31, wid = tid >> 5;
        #pragma unroll
        for (int o = 1; o < 32; o <<= 1) {
            int t = __shfl_up_sync(0xffffffffu, incl, o);
            if (lane >= o) incl += t;
        }
        if (lane == 31) wsum[wid] = incl;
        __syncthreads();
        if (wid == 0) {
            int s = wsum[lane];
            #pragma unroll
            for (int o = 1; o < 32; o <<= 1) {
                int t = __shfl_up_sync(0xffffffffu, s, o);
                if (lane >= o) s += t;
            }
            wsum[lane] = s;
        }
        __syncthreads();
        int off = (wid > 0) ? wsum[wid - 1] : 0;
        int excl = carry_s + off + incl - v;
        if (i < N_NODES) { g_rowptr[i] = excl; g_cursor[i] = excl; }
        __syncthreads();
        if (tid == 0) carry_s += wsum[31];
        __syncthreads();
    }
    if (tid == 0) g_rowptr[N_NODES] = carry_s;
}

__global__ void k_scatter() {
    int e = blockIdx.x * blockDim.x + threadIdx.x;
    if (e >= E_TOT) return;
    int pos = atomicAdd(&g_cursor[g_dst[e]], 1);
    g_perm[pos] = e;
}

// ---------------- edge attention scores ----------------
__global__ void k_edge_scores(const float* __restrict__ att) {
    int e = (blockIdx.x * blockDim.x + threadIdx.x) >> 5;
    int lane = threadIdx.x & 31;
    if (e >= E_TOT) return;
    const float4* pl = (const float4*)(g_xl + (size_t)g_src[e] * HC);
    const float4* pr = (const float4*)(g_xr + (size_t)g_dst[e] * HC);
    const float4* pa = (const float4*)att;
    float acc[4] = {0.f, 0.f, 0.f, 0.f};
    #pragma unroll
    for (int i = 0; i < 8; i++) {
        int idx = i * 32 + lane;
        float4 a = pl[idx], b = pr[idx], t = pa[idx];
        float mx = a.x + b.x, my = a.y + b.y, mz = a.z + b.z, mw = a.w + b.w;
        mx = mx > 0.f ? mx : 0.2f * mx;
        my = my > 0.f ? my : 0.2f * my;
        mz = mz > 0.f ? mz : 0.2f * mz;
        mw = mw > 0.f ? mw : 0.2f * mw;
        acc[i >> 1] += mx * t.x + my * t.y + mz * t.z + mw * t.w;
    }
    #pragma unroll
    for (int h = 0; h < 4; h++) {
        float v = acc[h];
        #pragma unroll
        for (int o = 16; o; o >>= 1) v += __shfl_xor_sync(0xffffffffu, v, o);
        if (lane == 0) g_esc[e * 4 + h] = v;
    }
}

__global__ void k_zero_soft() {
    int i = blockIdx.x * blockDim.x + threadIdx.x;
    if (i < N_NODES * 4) { g_emax[i] = 0u; g_den[i] = 0.f; }
}

__global__ void k_edge_max() {
    int i = blockIdx.x * blockDim.x + threadIdx.x;
    if (i >= E_TOT * 4) return;
    int e = i >> 2, h = i & 3;
    atomicMax(&g_emax[g_dst[e] * 4 + h], f2u(g_esc[i]));
}

__global__ void k_edge_exp() {
    int i = blockIdx.x * blockDim.x + threadIdx.x;
    if (i >= E_TOT * 4) return;
    int e = i >> 2, h = i & 3;
    int d = g_dst[e];
    float p = expf(g_esc[i] - u2f(g_emax[d * 4 + h]));
    g_esc[i] = p;
    atomicAdd(&g_den[d * 4 + h], p);
}

// ---- fused aggregation + LayerNorm + ELU + split-bf16 write ----
__global__ __launch_bounds__(256)
void k_agg_ln(const float* __restrict__ bias,
              const float* __restrict__ w, const float* __restrict__ b) {
    int n = blockIdx.x;
    int tid = threadIdx.x;
    float inv[4];
    #pragma unroll
    for (int h = 0; h < 4; h++) inv[h] = 1.f / (g_den[n * 4 + h] + 1e-16f);
    float acc[4] = {0.f, 0.f, 0.f, 0.f};
    int beg = g_rowptr[n], end = g_rowptr[n + 1];
    for (int j = beg; j < end; j++) {
        int e = g_perm[j];
        int s = g_src[e];
        float4 p = *(const float4*)&g_esc[e * 4];
        const float* row = g_xl + (size_t)s * HC;
        acc[0] = fmaf(p.x, row[tid      ], acc[0]);
        acc[1] = fmaf(p.y, row[tid + 256], acc[1]);
        acc[2] = fmaf(p.z, row[tid + 512], acc[2]);
        acc[3] = fmaf(p.w, row[tid + 768], acc[3]);
    }
    float v[4];
    float s = 0.f, s2 = 0.f;
    #pragma unroll
    for (int i = 0; i < 4; i++) {
        v[i] = acc[i] * inv[i] + bias[tid + i * 256];
        s += v[i];
        s2 += v[i] * v[i];
    }
    __shared__ float rs[8], rs2[8];
    int lane = tid & 31, wid = tid >> 5;
    #pragma unroll
    for (int o = 16; o; o >>= 1) {
        s  += __shfl_xor_sync(0xffffffffu, s,  o);
        s2 += __shfl_xor_sync(0xffffffffu, s2, o);
    }
    if (lane == 0) { rs[wid] = s; rs2[wid] = s2; }
    __syncthreads();
    if (tid == 0) {
        float a = 0.f, a2 = 0.f;
        #pragma unroll
        for (int i = 0; i < 8; i++) { a += rs[i]; a2 += rs2[i]; }
        rs[0] = a; rs2[0] = a2;
    }
    __syncthreads();
    float mu = rs[0] * (1.f / HC);
    float var = rs2[0] * (1.f / HC) - mu * mu;
    float r = rsqrtf(var + 1e-5f);
    size_t base = (size_t)n * KP2;
    #pragma unroll
    for (int i = 0; i < 4; i++) {
        int c = tid + i * 256;
        float y = (v[i] - mu) * r * w[c] + b[c];
        y = y > 0.f ? y : expm1f(y);
        __nv_bfloat16 hi = __float2bfloat16_rn(y);
        __nv_bfloat16 lo = __float2bfloat16_rn(y - __bfloat162float(hi));
        g_ahi[base + c] = hi;
        g_alo[base + c] = lo;
    }
}

// ---------------- classifier layer 2 ----------------
__global__ void k_cls2(const float* __restrict__ w2, const float* __restrict__ b2,
                       float* __restrict__ out) {
    __shared__ float sh[HID];
    int n = blockIdx.x;
    for (int i = threadIdx.x; i < HID; i += 64) sh[i] = g_cls[(size_t)n * HID + i];
    __syncthreads();
    int t = threadIdx.x;
    if (t < OUT_CH) {
        float a = b2[t];
        for (int k = 0; k < HID; k++) a = fmaf(sh[k], w2[k * OUT_CH + t], a);
        out[(size_t)n * OUT_CH + t] = a;
    }
}

// ---------------- launch ----------------
extern "C" void kernel_launch(void* const* d_in, const int* in_sizes, int n_in,
                              void* d_out, int out_size) {
    static const int MAP_INSERT[22] =
        {0,1,2,3,4,5,6,7,8,9,10,11,12,13,14,15,16,17,18,19,20,21};
    static const int MAP_ALPHA[22] =
        {21, 16, 4, 2, 5, 3, 0, 1, 18, 17,
         10, 8, 11, 9, 6, 7, 20, 19, 14, 12, 15, 13};
    const int* map = MAP_INSERT;
    if (n_in >= 22 && in_sizes[0] != N_NODES * IN_CH && in_sizes[21] == N_NODES * IN_CH)
        map = MAP_ALPHA;

    const float* x       = (const float*)d_in[map[0]];
    const void*  ei      = d_in[map[1]];
    const float* c1_wl   = (const float*)d_in[map[2]];
    const float* c1_bl   = (const float*)d_in[map[3]];
    const float* c1_wr   = (const float*)d_in[map[4]];
    const float* c1_br   = (const float*)d_in[map[5]];
    const float* c1_att  = (const float*)d_in[map[6]];
    const float* c1_bias = (const float*)d_in[map[7]];
    const float* ln1_w   = (const float*)d_in[map[8]];
    const float* ln1_b   = (const float*)d_in[map[9]];
    const float* c2_wl   = (const float*)d_in[map[10]];
    const float* c2_bl   = (const float*)d_in[map[11]];
    const float* c2_wr   = (const float*)d_in[map[12]];
    const float* c2_br   = (const float*)d_in[map[13]];
    const float* c2_att  = (const float*)d_in[map[14]];
    const float* c2_bias = (const float*)d_in[map[15]];
    const float* ln2_w   = (const float*)d_in[map[16]];
    const float* ln2_b   = (const float*)d_in[map[17]];
    const float* cls_w1  = (const float*)d_in[map[18]];
    const float* cls_b1  = (const float*)d_in[map[19]];
    const float* cls_w2  = (const float*)d_in[map[20]];
    const float* cls_b2  = (const float*)d_in[map[21]];
    float* out = (float*)d_out;

    cudaFuncSetAttribute(k_mma, cudaFuncAttributeMaxDynamicSharedMemorySize, SMEM_MMA);

    // CSR build
    k_detect<<<1, 1>>>((const unsigned long long*)ei);
    k_zero_csr<<<(N_NODES + 255) / 256, 256>>>();
    k_build<<<(E_TOT + 255) / 256, 256>>>(ei);
    k_scan<<<1, 1024>>>();
    k_scatter<<<(E_TOT + 255) / 256, 256>>>();

    int eb  = (E_TOT + 7) / 8;
    int e4b = (E_TOT * 4 + 255) / 256;
    int zb  = (N_NODES * 4 + 255) / 256;
    const int CB = 256;
    size_t a1_tot = (size_t)M_PAD * KP1;
    size_t b2tot1 = (size_t)2 * HC * KP1, b2tot2 = (size_t)2 * HC * KP2;

    // ---- conv1 (K=1030 -> 1088, merged wl+wr GEMM, N=2048) ----
    k_cvt_a<<<(int)((a1_tot + CB - 1) / CB), CB>>>(x, N_NODES, IN_CH, KP1, M_PAD);
    k_cvt_b2<<<(int)((b2tot1 + CB - 1) / CB), CB>>>(c1_wl, c1_wr, IN_CH, KP1);
    k_pack_bias<<<(2 * HC + 255) / 256, 256>>>(c1_bl, c1_br);
    {
        dim3 g(2 * HC / 128, (N_NODES + 127) / 128);
        k_mma<<<g, 256, SMEM_MMA>>>(3, nullptr, N_NODES, 2 * HC, KP1, 0);
    }
    k_edge_scores<<<eb, 256>>>(c1_att);
    k_zero_soft<<<zb, 256>>>();
    k_edge_max<<<e4b, 256>>>();
    k_edge_exp<<<e4b, 256>>>();
    k_agg_ln<<<N_NODES, 256>>>(c1_bias, ln1_w, ln1_b);

    // ---- conv2 (K=1024, merged GEMM) ----
    k_cvt_b2<<<(int)((b2tot2 + CB - 1) / CB), CB>>>(c2_wl, c2_wr, HC, KP2);
    k_pack_bias<<<(2 * HC + 255) / 256, 256>>>(c2_bl, c2_br);
    {
        dim3 g(2 * HC / 128, (N_NODES + 127) / 128);
        k_mma<<<g, 256, SMEM_MMA>>>(3, nullptr, N_NODES, 2 * HC, KP2, 0);
    }
    k_edge_scores<<<eb, 256>>>(c2_att);
    k_zero_soft<<<zb, 256>>>();
    k_edge_max<<<e4b, 256>>>();
    k_edge_exp<<<e4b, 256>>>();
    k_agg_ln<<<N_NODES, 256>>>(c2_bias, ln2_w, ln2_b);

    // ---- classifier ----
    k_cvt_b<<<(int)(((size_t)HID * KP2 + CB - 1) / CB), CB>>>(cls_w1, HC, HID, KP2);
    {
        dim3 g(HID / 128, (N_NODES + 127) / 128);
        k_mma<<<g, 256, SMEM_MMA>>>(2, cls_b1, N_NODES, HID, KP2, 1);
    }
    k_cls2<<<N_NODES, 64>>>(cls_w2, cls_b2, out);
}

// round 11
// speedup vs baseline: 2.6898x; 1.0166x over previous
#include <cuda_runtime.h>
#include <cuda_bf16.h>
#include <math.h>
#include <stdint.h>

#define N_NODES 10000
#define N_EDGES 160000
#define E_TOT   170000
#define IN_CH   1030
#define HC      1024
#define HID     256
#define OUT_CH  49
#define M_PAD   10112          // 79 * 128
#define KP1     1088
#define KP2     1024

// ---------------- device scratch ----------------
__device__ float g_xl[(size_t)N_NODES * HC];
__device__ float g_xr[(size_t)N_NODES * HC];
__device__ float g_cls[(size_t)N_NODES * HID];
__device__ float g_bias2[2 * HC];
__device__ __align__(128) __nv_bfloat16 g_ahi[(size_t)M_PAD * KP1];
__device__ __align__(128) __nv_bfloat16 g_alo[(size_t)M_PAD * KP1];
__device__ __align__(128) __nv_bfloat16 g_bhi[(size_t)2 * HC * KP1];
__device__ __align__(128) __nv_bfloat16 g_blo[(size_t)2 * HC * KP1];
__device__ int      g_src[E_TOT];
__device__ int      g_dst[E_TOT];
__device__ float    g_esc[E_TOT * 4];
__device__ unsigned g_emax[N_NODES * 4];
__device__ int g_cnt[N_NODES];
__device__ int g_rowptr[N_NODES + 1];
__device__ int g_cursor[N_NODES];
__device__ int g_perm[E_TOT];
__device__ int g_ei_is64;

__device__ __forceinline__ unsigned f2u(float f) {
    unsigned u = __float_as_uint(f);
    return (u & 0x80000000u) ? ~u : (u | 0x80000000u);
}
__device__ __forceinline__ float u2f(unsigned u) {
    return (u & 0x80000000u) ? __uint_as_float(u & 0x7fffffffu) : __uint_as_float(~u);
}

// ---------------- asm helpers ----------------
__device__ __forceinline__ uint32_t smem_u32(const void* p) {
    uint32_t a;
    asm("{ .reg .u64 t; cvta.to.shared.u64 t, %1; cvt.u32.u64 %0, t; }" : "=r"(a) : "l"(p));
    return a;
}
__device__ __forceinline__ void cp_async16(uint32_t dst, const void* src) {
    asm volatile("cp.async.cg.shared.global [%0], [%1], 16;" :: "r"(dst), "l"(src));
}
#define CP_COMMIT() asm volatile("cp.async.commit_group;")
#define CP_WAIT0()  asm volatile("cp.async.wait_group 0;" ::: "memory")
#define CP_WAIT1()  asm volatile("cp.async.wait_group 1;" ::: "memory")

__device__ __forceinline__ void ldsm4(uint32_t* r, uint32_t addr) {
    asm volatile("ldmatrix.sync.aligned.m8n8.x4.shared.b16 {%0,%1,%2,%3}, [%4];"
        : "=r"(r[0]), "=r"(r[1]), "=r"(r[2]), "=r"(r[3]) : "r"(addr));
}
__device__ __forceinline__ void mma16816(float* c, const uint32_t* a,
                                         uint32_t b0, uint32_t b1) {
    asm volatile(
        "mma.sync.aligned.m16n8k16.row.col.f32.bf16.bf16.f32 "
        "{%0,%1,%2,%3}, {%4,%5,%6,%7}, {%8,%9}, {%0,%1,%2,%3};"
        : "+f"(c[0]), "+f"(c[1]), "+f"(c[2]), "+f"(c[3])
        : "r"(a[0]), "r"(a[1]), "r"(a[2]), "r"(a[3]), "r"(b0), "r"(b1));
}

// ---------------- conversions ----------------
__global__ void k_cvt_a(const float* __restrict__ A, int M_real, int K_real,
                        int K_pad, int M_use) {
    size_t idx = (size_t)blockIdx.x * blockDim.x + threadIdx.x;
    size_t tot = (size_t)M_use * K_pad;
    if (idx >= tot) return;
    int r = (int)(idx / K_pad), c = (int)(idx % K_pad);
    float x = (r < M_real && c < K_real) ? A[(size_t)r * K_real + c] : 0.f;
    __nv_bfloat16 hi = __float2bfloat16_rn(x);
    __nv_bfloat16 lo = __float2bfloat16_rn(x - __bfloat162float(hi));
    g_ahi[idx] = hi;
    g_alo[idx] = lo;
}

// two [K_real,1024] weights -> [2048, K_pad] split-bf16; also packs biases
__global__ void k_cvt_b2(const float* __restrict__ Bl, const float* __restrict__ Br,
                         const float* __restrict__ bl, const float* __restrict__ br,
                         int K_real, int K_pad) {
    size_t idx = (size_t)blockIdx.x * blockDim.x + threadIdx.x;
    if (idx < 2 * HC) g_bias2[idx] = (idx < HC) ? bl[idx] : br[idx - HC];
    size_t tot = (size_t)2 * HC * K_pad;
    if (idx >= tot) return;
    int n = (int)(idx / K_pad), k = (int)(idx % K_pad);
    const float* B = (n < HC) ? Bl : Br;
    int nn = (n < HC) ? n : n - HC;
    float x = (k < K_real) ? B[(size_t)k * HC + nn] : 0.f;
    __nv_bfloat16 hi = __float2bfloat16_rn(x);
    __nv_bfloat16 lo = __float2bfloat16_rn(x - __bfloat162float(hi));
    g_bhi[idx] = hi;
    g_blo[idx] = lo;
}

__global__ void k_cvt_b(const float* __restrict__ B, int K_real, int N, int K_pad) {
    size_t idx = (size_t)blockIdx.x * blockDim.x + threadIdx.x;
    size_t tot = (size_t)N * K_pad;
    if (idx >= tot) return;
    int n = (int)(idx / K_pad), k = (int)(idx % K_pad);
    float x = (k < K_real) ? B[(size_t)k * N + n] : 0.f;
    __nv_bfloat16 hi = __float2bfloat16_rn(x);
    __nv_bfloat16 lo = __float2bfloat16_rn(x - __bfloat162float(hi));
    g_bhi[idx] = hi;
    g_blo[idx] = lo;
}

// ---------------- mma.sync split-bf16 GEMM (ldmatrix, 2-stage, 2 CTA/SM) ----
#define ROWB   80
#define TIL    (128 * ROWB)
#define STG    (4 * TIL)        // 40960
#define SMEM_MMA (2 * STG)      // 80KB

__device__ __forceinline__ void load_stage(uint32_t sb, int it, int tid,
                                           const __nv_bfloat16* s0, const __nv_bfloat16* s1,
                                           const __nv_bfloat16* s2, const __nv_bfloat16* s3,
                                           int K_pad) {
    uint32_t stage = sb + (uint32_t)(it & 1) * STG;
    int k0 = it * 32;
    const __nv_bfloat16* srcs[4] = {s0, s1, s2, s3};
    #pragma unroll
    for (int q = 0; q < 8; q++) {
        int id = tid + q * 256;
        int t = id >> 9, r = (id >> 2) & 127, u = id & 3;
        cp_async16(stage + t * TIL + r * ROWB + u * 16,
                   srcs[t] + (size_t)r * K_pad + k0 + u * 8);
    }
    CP_COMMIT();
}

// c_sel: 2 = g_cls (bias, act), 3 = split g_xl/g_xr (g_bias2)
__global__ __launch_bounds__(256)
void k_mma(int c_sel, const float* __restrict__ bias,
           int M, int N_tot, int K_pad, int act) {
    extern __shared__ char sm[];
    int tid = threadIdx.x, w = tid >> 5, l = tid & 31;
    int wm = w >> 1, wn = w & 1;
    int bm = blockIdx.y * 128, bn = blockIdx.x * 128;
    uint32_t sb = smem_u32(sm);
    int q = l >> 3;

    uint32_t aoff = (uint32_t)((wm * 32 + ((q & 1) << 3) + (l & 7)) * ROWB + ((q >> 1) << 4));
    uint32_t boff = (uint32_t)((wn * 64 + ((q >> 1) << 3) + (l & 7)) * ROWB + ((q & 1) << 4));

    const __nv_bfloat16* sA_hi = g_ahi + (size_t)bm * K_pad;
    const __nv_bfloat16* sA_lo = g_alo + (size_t)bm * K_pad;
    const __nv_bfloat16* sB_hi = g_bhi + (size_t)bn * K_pad;
    const __nv_bfloat16* sB_lo = g_blo + (size_t)bn * K_pad;

    float acc[2][8][4];
    #pragma unroll
    for (int m = 0; m < 2; m++)
        #pragma unroll
        for (int n = 0; n < 8; n++)
            #pragma unroll
            for (int i = 0; i < 4; i++) acc[m][n][i] = 0.f;

    int nk = K_pad / 32;
    load_stage(sb, 0, tid, sA_hi, sA_lo, sB_hi, sB_lo, K_pad);
    load_stage(sb, 1, tid, sA_hi, sA_lo, sB_hi, sB_lo, K_pad);

    for (int it = 0; it < nk; it++) {
        if (it == nk - 1) { CP_WAIT0(); } else { CP_WAIT1(); }
        __syncthreads();
        uint32_t stage = sb + (uint32_t)(it & 1) * STG;
        #pragma unroll
        for (int pass = 0; pass < 3; pass++) {
            uint32_t pA = stage + ((pass < 2) ? 0u : (uint32_t)TIL);
            uint32_t pB = stage + ((pass == 1) ? 3u * TIL : 2u * TIL);
            #pragma unroll
            for (int kc = 0; kc < 2; kc++) {
                uint32_t a[2][4], b[4][4];
                ldsm4(a[0], pA + aoff + kc * 32);
                ldsm4(a[1], pA + aoff + 16 * ROWB + kc * 32);
                #pragma unroll
                for (int p = 0; p < 4; p++)
                    ldsm4(b[p], pB + boff + p * (16 * ROWB) + kc * 32);
                #pragma unroll
                for (int n = 0; n < 8; n++) {
                    uint32_t b0 = b[n >> 1][(n & 1) * 2];
                    uint32_t b1 = b[n >> 1][(n & 1) * 2 + 1];
                    mma16816(acc[0][n], a[0], b0, b1);
                    mma16816(acc[1][n], a[1], b0, b1);
                }
            }
        }
        __syncthreads();
        if (it + 2 < nk) load_stage(sb, it + 2, tid, sA_hi, sA_lo, sB_hi, sB_lo, K_pad);
    }

    #pragma unroll
    for (int m = 0; m < 2; m++) {
        #pragma unroll
        for (int n = 0; n < 8; n++) {
            int cglob = bn + wn * 64 + n * 8 + (l & 3) * 2;
            float* Cp;
            int cc;
            float2 bv;
            if (c_sel == 3) {
                bool right = cglob >= HC;
                Cp = right ? g_xr : g_xl;
                cc = right ? cglob - HC : cglob;
                bv = *(const float2*)(g_bias2 + cglob);
            } else {
                Cp = g_cls;
                cc = cglob;
                bv = *(const float2*)(bias + cglob);
            }
            int stride = (c_sel == 3) ? HC : N_tot;
            int r0 = bm + wm * 32 + m * 16 + (l >> 2);
            #pragma unroll
            for (int hh = 0; hh < 2; hh++) {
                int row = r0 + hh * 8;
                if (row < M) {
                    float vx = acc[m][n][hh * 2    ] + bv.x;
                    float vy = acc[m][n][hh * 2 + 1] + bv.y;
                    if (act == 1) {
                        vx = vx > 0.f ? vx : expm1f(vx);
                        vy = vy > 0.f ? vy : expm1f(vy);
                    }
                    *(float2*)(Cp + (size_t)row * stride + cc) = make_float2(vx, vy);
                }
            }
        }
    }
}

// ---------------- edge_index dtype detection ----------------
__global__ void k_detect(const unsigned long long* __restrict__ ei64) {
    int is64 = 1;
    for (int i = 0; i < 64; i++)
        if (ei64[i] >= (1ULL << 32)) { is64 = 0; break; }
    g_ei_is64 = is64;
}

// ---------------- CSR build ----------------
__global__ void k_zero_csr() {
    int i = blockIdx.x * blockDim.x + threadIdx.x;
    if (i < N_NODES) g_cnt[i] = 0;
}

__global__ void k_build(const void* __restrict__ ei) {
    int i = blockIdx.x * blockDim.x + threadIdx.x;
    if (i >= E_TOT) return;
    int s, d;
    if (i < N_EDGES) {
        if (g_ei_is64) {
            const long long* p = (const long long*)ei;
            s = (int)p[i]; d = (int)p[N_EDGES + i];
        } else {
            const int* p = (const int*)ei;
            s = p[i]; d = p[N_EDGES + i];
        }
    } else {
        s = d = i - N_EDGES;
    }
    if ((unsigned)s >= N_NODES) s = 0;
    if ((unsigned)d >= N_NODES) d = 0;
    g_src[i] = s;
    g_dst[i] = d;
    atomicAdd(&g_cnt[d], 1);
}

__global__ void k_scan() {
    __shared__ int wsum[32];
    __shared__ int carry_s;
    int tid = threadIdx.x;
    if (tid == 0) carry_s = 0;
    __syncthreads();
    for (int base = 0; base < N_NODES; base += 1024) {
        int i = base + tid;
        int v = (i < N_NODES) ? g_cnt[i] : 0;
        int incl = v;
        int lane = tid & 31, wid = tid >> 5;
        #pragma unroll
        for (int o = 1; o < 32; o <<= 1) {
            int t = __shfl_up_sync(0xffffffffu, incl, o);
            if (lane >= o) incl += t;
        }
        if (lane == 31) wsum[wid] = incl;
        __syncthreads();
        if (wid == 0) {
            int s = wsum[lane];
            #pragma unroll
            for (int o = 1; o < 32; o <<= 1) {
                int t = __shfl_up_sync(0xffffffffu, s, o);
                if (lane >= o) s += t;
            }
            wsum[lane] = s;
        }
        __syncthreads();
        int off = (wid > 0) ? wsum[wid - 1] : 0;
        int excl = carry_s + off + incl - v;
        if (i < N_NODES) { g_rowptr[i] = excl; g_cursor[i] = excl; }
        __syncthreads();
        if (tid == 0) carry_s += wsum[31];
        __syncthreads();
    }
    if (tid == 0) g_rowptr[N_NODES] = carry_s;
}

__global__ void k_scatter() {
    int e = blockIdx.x * blockDim.x + threadIdx.x;
    if (e >= E_TOT) return;
    int pos = atomicAdd(&g_cursor[g_dst[e]], 1);
    g_perm[pos] = e;
}

// ---------------- edge scores + fused atomicMax ----------------
__global__ void k_edge_scores(const float* __restrict__ att) {
    int e = (blockIdx.x * blockDim.x + threadIdx.x) >> 5;
    int lane = threadIdx.x & 31;
    if (e >= E_TOT) return;
    int se = g_src[e], de = g_dst[e];
    const float4* pl = (const float4*)(g_xl + (size_t)se * HC);
    const float4* pr = (const float4*)(g_xr + (size_t)de * HC);
    const float4* pa = (const float4*)att;
    float acc[4] = {0.f, 0.f, 0.f, 0.f};
    #pragma unroll
    for (int i = 0; i < 8; i++) {
        int idx = i * 32 + lane;
        float4 a = pl[idx], b = pr[idx], t = pa[idx];
        float mx = a.x + b.x, my = a.y + b.y, mz = a.z + b.z, mw = a.w + b.w;
        mx = mx > 0.f ? mx : 0.2f * mx;
        my = my > 0.f ? my : 0.2f * my;
        mz = mz > 0.f ? mz : 0.2f * mz;
        mw = mw > 0.f ? mw : 0.2f * mw;
        acc[i >> 1] += mx * t.x + my * t.y + mz * t.z + mw * t.w;
    }
    #pragma unroll
    for (int h = 0; h < 4; h++) {
        float v = acc[h];
        #pragma unroll
        for (int o = 16; o; o >>= 1) v += __shfl_xor_sync(0xffffffffu, v, o);
        if (lane == 0) {
            g_esc[e * 4 + h] = v;
            atomicMax(&g_emax[de * 4 + h], f2u(v));
        }
    }
}

__global__ void k_zero_max() {
    int i = blockIdx.x * blockDim.x + threadIdx.x;
    if (i < N_NODES * 4) g_emax[i] = 0u;
}

// exp per edge (float4), no atomics
__global__ void k_edge_exp() {
    int e = blockIdx.x * blockDim.x + threadIdx.x;
    if (e >= E_TOT) return;
    int d = g_dst[e];
    uint4 mu = *(const uint4*)&g_emax[d * 4];
    float4 p = *(const float4*)&g_esc[e * 4];
    p.x = expf(p.x - u2f(mu.x));
    p.y = expf(p.y - u2f(mu.y));
    p.z = expf(p.z - u2f(mu.z));
    p.w = expf(p.w - u2f(mu.w));
    *(float4*)&g_esc[e * 4] = p;
}

// ---- fused aggregation + in-register den + LayerNorm + ELU + split-bf16 ----
__global__ __launch_bounds__(256)
void k_agg_ln(const float* __restrict__ bias,
              const float* __restrict__ w, const float* __restrict__ b) {
    int n = blockIdx.x;
    int tid = threadIdx.x;
    float acc[4] = {0.f, 0.f, 0.f, 0.f};
    float den[4] = {0.f, 0.f, 0.f, 0.f};
    int beg = g_rowptr[n], end = g_rowptr[n + 1];
    for (int j = beg; j < end; j++) {
        int e = g_perm[j];
        int s = g_src[e];
        float4 p = *(const float4*)&g_esc[e * 4];
        den[0] += p.x; den[1] += p.y; den[2] += p.z; den[3] += p.w;
        const float* row = g_xl + (size_t)s * HC;
        acc[0] = fmaf(p.x, row[tid      ], acc[0]);
        acc[1] = fmaf(p.y, row[tid + 256], acc[1]);
        acc[2] = fmaf(p.z, row[tid + 512], acc[2]);
        acc[3] = fmaf(p.w, row[tid + 768], acc[3]);
    }
    float v[4];
    float s = 0.f, s2 = 0.f;
    #pragma unroll
    for (int i = 0; i < 4; i++) {
        v[i] = acc[i] / (den[i] + 1e-16f) + bias[tid + i * 256];
        s += v[i];
        s2 += v[i] * v[i];
    }
    __shared__ float rs[8], rs2[8];
    int lane = tid & 31, wid = tid >> 5;
    #pragma unroll
    for (int o = 16; o; o >>= 1) {
        s  += __shfl_xor_sync(0xffffffffu, s,  o);
        s2 += __shfl_xor_sync(0xffffffffu, s2, o);
    }
    if (lane == 0) { rs[wid] = s; rs2[wid] = s2; }
    __syncthreads();
    if (tid == 0) {
        float a = 0.f, a2 = 0.f;
        #pragma unroll
        for (int i = 0; i < 8; i++) { a += rs[i]; a2 += rs2[i]; }
        rs[0] = a; rs2[0] = a2;
    }
    __syncthreads();
    float mu = rs[0] * (1.f / HC);
    float var = rs2[0] * (1.f / HC) - mu * mu;
    float r = rsqrtf(var + 1e-5f);
    size_t base = (size_t)n * KP2;
    #pragma unroll
    for (int i = 0; i < 4; i++) {
        int c = tid + i * 256;
        float y = (v[i] - mu) * r * w[c] + b[c];
        y = y > 0.f ? y : expm1f(y);
        __nv_bfloat16 hi = __float2bfloat16_rn(y);
        __nv_bfloat16 lo = __float2bfloat16_rn(y - __bfloat162float(hi));
        g_ahi[base + c] = hi;
        g_alo[base + c] = lo;
    }
}

// ---------------- classifier layer 2 (tiled: 32 nodes/block) ----------------
#define CLS_N   32
#define SMEM_CLS ((HID * OUT_CH + CLS_N * HID) * 4)   // 82944 B
__global__ __launch_bounds__(256)
void k_cls2(const float* __restrict__ w2, const float* __restrict__ b2,
            float* __restrict__ out) {
    extern __shared__ float smc[];
    float* sw  = smc;                    // [HID * OUT_CH], layout w2[k*49+j]
    float* shh = smc + HID * OUT_CH;     // [CLS_N * HID]
    int tid = threadIdx.x;
    int base = blockIdx.x * CLS_N;
    for (int i = tid; i < HID * OUT_CH; i += 256) sw[i] = w2[i];
    for (int i = tid; i < CLS_N * HID; i += 256) {
        int n = i >> 8, c = i & 255;
        int gn = base + n;
        shh[i] = (gn < N_NODES) ? g_cls[(size_t)gn * HID + c] : 0.f;
    }
    __syncthreads();
    int j = tid & 63, grp = tid >> 6;    // 4 groups of 64; j < 49 active
    if (j < OUT_CH) {
        float bj = b2[j];
        for (int n = grp; n < CLS_N; n += 4) {
            int gn = base + n;
            if (gn >= N_NODES) break;
            const float4* hr = (const float4*)(shh + n * HID);
            float a = bj;
            #pragma unroll 16
            for (int k4 = 0; k4 < HID / 4; k4++) {
                float4 h4 = hr[k4];
                int k = k4 * 4;
                a = fmaf(h4.x, sw[(k    ) * OUT_CH + j], a);
                a = fmaf(h4.y, sw[(k + 1) * OUT_CH + j], a);
                a = fmaf(h4.z, sw[(k + 2) * OUT_CH + j], a);
                a = fmaf(h4.w, sw[(k + 3) * OUT_CH + j], a);
            }
            out[(size_t)gn * OUT_CH + j] = a;
        }
    }
}

// ---------------- launch ----------------
extern "C" void kernel_launch(void* const* d_in, const int* in_sizes, int n_in,
                              void* d_out, int out_size) {
    static const int MAP_INSERT[22] =
        {0,1,2,3,4,5,6,7,8,9,10,11,12,13,14,15,16,17,18,19,20,21};
    static const int MAP_ALPHA[22] =
        {21, 16, 4, 2, 5, 3, 0, 1, 18, 17,
         10, 8, 11, 9, 6, 7, 20, 19, 14, 12, 15, 13};
    const int* map = MAP_INSERT;
    if (n_in >= 22 && in_sizes[0] != N_NODES * IN_CH && in_sizes[21] == N_NODES * IN_CH)
        map = MAP_ALPHA;

    const float* x       = (const float*)d_in[map[0]];
    const void*  ei      = d_in[map[1]];
    const float* c1_wl   = (const float*)d_in[map[2]];
    const float* c1_bl   = (const float*)d_in[map[3]];
    const float* c1_wr   = (const float*)d_in[map[4]];
    const float* c1_br   = (const float*)d_in[map[5]];
    const float* c1_att  = (const float*)d_in[map[6]];
    const float* c1_bias = (const float*)d_in[map[7]];
    const float* ln1_w   = (const float*)d_in[map[8]];
    const float* ln1_b   = (const float*)d_in[map[9]];
    const float* c2_wl   = (const float*)d_in[map[10]];
    const float* c2_bl   = (const float*)d_in[map[11]];
    const float* c2_wr   = (const float*)d_in[map[12]];
    const float* c2_br   = (const float*)d_in[map[13]];
    const float* c2_att  = (const float*)d_in[map[14]];
    const float* c2_bias = (const float*)d_in[map[15]];
    const float* ln2_w   = (const float*)d_in[map[16]];
    const float* ln2_b   = (const float*)d_in[map[17]];
    const float* cls_w1  = (const float*)d_in[map[18]];
    const float* cls_b1  = (const float*)d_in[map[19]];
    const float* cls_w2  = (const float*)d_in[map[20]];
    const float* cls_b2  = (const float*)d_in[map[21]];
    float* out = (float*)d_out;

    cudaFuncSetAttribute(k_mma, cudaFuncAttributeMaxDynamicSharedMemorySize, SMEM_MMA);
    cudaFuncSetAttribute(k_cls2, cudaFuncAttributeMaxDynamicSharedMemorySize, SMEM_CLS);

    // CSR build
    k_detect<<<1, 1>>>((const unsigned long long*)ei);
    k_zero_csr<<<(N_NODES + 255) / 256, 256>>>();
    k_build<<<(E_TOT + 255) / 256, 256>>>(ei);
    k_scan<<<1, 1024>>>();
    k_scatter<<<(E_TOT + 255) / 256, 256>>>();
    k_zero_max<<<(N_NODES * 4 + 255) / 256, 256>>>();

    int eb = (E_TOT + 7) / 8;
    int e1b = (E_TOT + 255) / 256;
    int zb  = (N_NODES * 4 + 255) / 256;
    const int CB = 256;
    size_t a1_tot = (size_t)M_PAD * KP1;
    size_t b2tot1 = (size_t)2 * HC * KP1, b2tot2 = (size_t)2 * HC * KP2;

    // ---- conv1 ----
    k_cvt_a<<<(int)((a1_tot + CB - 1) / CB), CB>>>(x, N_NODES, IN_CH, KP1, M_PAD);
    k_cvt_b2<<<(int)((b2tot1 + CB - 1) / CB), CB>>>(c1_wl, c1_wr, c1_bl, c1_br, IN_CH, KP1);
    {
        dim3 g(2 * HC / 128, (N_NODES + 127) / 128);
        k_mma<<<g, 256, SMEM_MMA>>>(3, nullptr, N_NODES, 2 * HC, KP1, 0);
    }
    k_edge_scores<<<eb, 256>>>(c1_att);
    k_edge_exp<<<e1b, 256>>>();
    k_zero_max<<<zb, 256>>>();                         // reset for layer 2
    k_agg_ln<<<N_NODES, 256>>>(c1_bias, ln1_w, ln1_b);

    // ---- conv2 ----
    k_cvt_b2<<<(int)((b2tot2 + CB - 1) / CB), CB>>>(c2_wl, c2_wr, c2_bl, c2_br, HC, KP2);
    {
        dim3 g(2 * HC / 128, (N_NODES + 127) / 128);
        k_mma<<<g, 256, SMEM_MMA>>>(3, nullptr, N_NODES, 2 * HC, KP2, 0);
    }
    k_edge_scores<<<eb, 256>>>(c2_att);
    k_edge_exp<<<e1b, 256>>>();
    k_agg_ln<<<N_NODES, 256>>>(c2_bias, ln2_w, ln2_b);

    // ---- classifier ----
    k_cvt_b<<<(int)(((size_t)HID * KP2 + CB - 1) / CB), CB>>>(cls_w1, HC, HID, KP2);
    {
        dim3 g(HID / 128, (N_NODES + 127) / 128);
        k_mma<<<g, 256, SMEM_MMA>>>(2, cls_b1, N_NODES, HID, KP2, 1);
    }
    k_cls2<<<(N_NODES + CLS_N - 1) / CLS_N, 256, SMEM_CLS>>>(cls_w2, cls_b2, out);
}

// round 12
// speedup vs baseline: 2.7952x; 1.0392x over previous
#include <cuda_runtime.h>
#include <cuda_bf16.h>
#include <math.h>
#include <stdint.h>

#define N_NODES 10000
#define N_EDGES 160000
#define E_TOT   170000
#define IN_CH   1030
#define HC      1024
#define HID     256
#define OUT_CH  49
#define M_PAD   10112
#define KP1     1088
#define KP2     1024

// ---------------- device scratch ----------------
__device__ float g_xl[(size_t)N_NODES * HC];
__device__ float g_xr[(size_t)N_NODES * HC];
__device__ float g_cls[(size_t)N_NODES * HID];
__device__ float g_bias2[2 * HC];
__device__ __align__(128) __nv_bfloat16 g_ahi[(size_t)M_PAD * KP1];
__device__ __align__(128) __nv_bfloat16 g_alo[(size_t)M_PAD * KP1];
__device__ __align__(128) __nv_bfloat16 g_bhi[(size_t)2 * HC * KP1];
__device__ __align__(128) __nv_bfloat16 g_blo[(size_t)2 * HC * KP1];
__device__ int      g_src[E_TOT];
__device__ int      g_dst[E_TOT];
__device__ float    g_esc[E_TOT * 4];
__device__ int g_cnt[N_NODES];
__device__ int g_rowptr[N_NODES + 1];
__device__ int g_cursor[N_NODES];
__device__ int g_perm[E_TOT];
__device__ int g_ei_is64;

// ---------------- asm helpers ----------------
__device__ __forceinline__ uint32_t smem_u32(const void* p) {
    uint32_t a;
    asm("{ .reg .u64 t; cvta.to.shared.u64 t, %1; cvt.u32.u64 %0, t; }" : "=r"(a) : "l"(p));
    return a;
}
__device__ __forceinline__ void cp_async16(uint32_t dst, const void* src) {
    asm volatile("cp.async.cg.shared.global [%0], [%1], 16;" :: "r"(dst), "l"(src));
}
#define CP_COMMIT() asm volatile("cp.async.commit_group;")
#define CP_WAIT0()  asm volatile("cp.async.wait_group 0;" ::: "memory")
#define CP_WAIT1()  asm volatile("cp.async.wait_group 1;" ::: "memory")

__device__ __forceinline__ void ldsm4(uint32_t* r, uint32_t addr) {
    asm volatile("ldmatrix.sync.aligned.m8n8.x4.shared.b16 {%0,%1,%2,%3}, [%4];"
        : "=r"(r[0]), "=r"(r[1]), "=r"(r[2]), "=r"(r[3]) : "r"(addr));
}
__device__ __forceinline__ void mma16816(float* c, const uint32_t* a,
                                         uint32_t b0, uint32_t b1) {
    asm volatile(
        "mma.sync.aligned.m16n8k16.row.col.f32.bf16.bf16.f32 "
        "{%0,%1,%2,%3}, {%4,%5,%6,%7}, {%8,%9}, {%0,%1,%2,%3};"
        : "+f"(c[0]), "+f"(c[1]), "+f"(c[2]), "+f"(c[3])
        : "r"(a[0]), "r"(a[1]), "r"(a[2]), "r"(a[3]), "r"(b0), "r"(b1));
}

// ---------------- conversions ----------------
__global__ void k_cvt_a(const float* __restrict__ A, int M_real, int K_real,
                        int K_pad, int M_use) {
    size_t idx = (size_t)blockIdx.x * blockDim.x + threadIdx.x;
    size_t tot = (size_t)M_use * K_pad;
    if (idx >= tot) return;
    int r = (int)(idx / K_pad), c = (int)(idx % K_pad);
    float x = (r < M_real && c < K_real) ? A[(size_t)r * K_real + c] : 0.f;
    __nv_bfloat16 hi = __float2bfloat16_rn(x);
    __nv_bfloat16 lo = __float2bfloat16_rn(x - __bfloat162float(hi));
    g_ahi[idx] = hi;
    g_alo[idx] = lo;
}

__global__ void k_cvt_b2(const float* __restrict__ Bl, const float* __restrict__ Br,
                         const float* __restrict__ bl, const float* __restrict__ br,
                         int K_real, int K_pad) {
    size_t idx = (size_t)blockIdx.x * blockDim.x + threadIdx.x;
    if (idx < 2 * HC) g_bias2[idx] = (idx < HC) ? bl[idx] : br[idx - HC];
    size_t tot = (size_t)2 * HC * K_pad;
    if (idx >= tot) return;
    int n = (int)(idx / K_pad), k = (int)(idx % K_pad);
    const float* B = (n < HC) ? Bl : Br;
    int nn = (n < HC) ? n : n - HC;
    float x = (k < K_real) ? B[(size_t)k * HC + nn] : 0.f;
    __nv_bfloat16 hi = __float2bfloat16_rn(x);
    __nv_bfloat16 lo = __float2bfloat16_rn(x - __bfloat162float(hi));
    g_bhi[idx] = hi;
    g_blo[idx] = lo;
}

__global__ void k_cvt_b(const float* __restrict__ B, int K_real, int N, int K_pad) {
    size_t idx = (size_t)blockIdx.x * blockDim.x + threadIdx.x;
    size_t tot = (size_t)N * K_pad;
    if (idx >= tot) return;
    int n = (int)(idx / K_pad), k = (int)(idx % K_pad);
    float x = (k < K_real) ? B[(size_t)k * N + n] : 0.f;
    __nv_bfloat16 hi = __float2bfloat16_rn(x);
    __nv_bfloat16 lo = __float2bfloat16_rn(x - __bfloat162float(hi));
    g_bhi[idx] = hi;
    g_blo[idx] = lo;
}

// ---------------- mma.sync split-bf16 GEMM ----------------
#define ROWB   80
#define TIL    (128 * ROWB)
#define STG    (4 * TIL)        // 40960
#define SMEM_MMA (2 * STG)      // 80KB -> 2 CTA/SM

__device__ __forceinline__ void load_stage(uint32_t sb, int it, int tid,
                                           const __nv_bfloat16* s0, const __nv_bfloat16* s1,
                                           const __nv_bfloat16* s2, const __nv_bfloat16* s3,
                                           int K_pad) {
    uint32_t stage = sb + (uint32_t)(it & 1) * STG;
    int k0 = it * 32;
    const __nv_bfloat16* srcs[4] = {s0, s1, s2, s3};
    #pragma unroll
    for (int q = 0; q < 8; q++) {
        int id = tid + q * 256;
        int t = id >> 9, r = (id >> 2) & 127, u = id & 3;
        cp_async16(stage + t * TIL + r * ROWB + u * 16,
                   srcs[t] + (size_t)r * K_pad + k0 + u * 8);
    }
    CP_COMMIT();
}

// c_sel: 2 = g_cls (bias, act), 3 = split g_xl/g_xr (g_bias2)
__global__ __launch_bounds__(256)
void k_mma(int c_sel, const float* __restrict__ bias,
           int M, int N_tot, int K_pad, int act) {
    extern __shared__ char sm[];
    int tid = threadIdx.x, w = tid >> 5, l = tid & 31;
    int wm = w >> 1, wn = w & 1;
    int bm = blockIdx.y * 128, bn = blockIdx.x * 128;
    uint32_t sb = smem_u32(sm);
    int q = l >> 3;

    uint32_t aoff = (uint32_t)((wm * 32 + ((q & 1) << 3) + (l & 7)) * ROWB + ((q >> 1) << 4));
    uint32_t boff = (uint32_t)((wn * 64 + ((q >> 1) << 3) + (l & 7)) * ROWB + ((q & 1) << 4));

    const __nv_bfloat16* sA_hi = g_ahi + (size_t)bm * K_pad;
    const __nv_bfloat16* sA_lo = g_alo + (size_t)bm * K_pad;
    const __nv_bfloat16* sB_hi = g_bhi + (size_t)bn * K_pad;
    const __nv_bfloat16* sB_lo = g_blo + (size_t)bn * K_pad;

    float acc[2][8][4];
    #pragma unroll
    for (int m = 0; m < 2; m++)
        #pragma unroll
        for (int n = 0; n < 8; n++)
            #pragma unroll
            for (int i = 0; i < 4; i++) acc[m][n][i] = 0.f;

    int nk = K_pad / 32;
    load_stage(sb, 0, tid, sA_hi, sA_lo, sB_hi, sB_lo, K_pad);
    load_stage(sb, 1, tid, sA_hi, sA_lo, sB_hi, sB_lo, K_pad);

    for (int it = 0; it < nk; it++) {
        if (it == nk - 1) { CP_WAIT0(); } else { CP_WAIT1(); }
        __syncthreads();
        uint32_t stage = sb + (uint32_t)(it & 1) * STG;
        uint32_t pAhi = stage, pAlo = stage + TIL;
        uint32_t pBhi = stage + 2u * TIL, pBlo = stage + 3u * TIL;
        #pragma unroll
        for (int kc = 0; kc < 2; kc++) {
            uint32_t koff = kc * 32;
            uint32_t ah[2][4], al[2][4], b[4][4];
            // load each fragment set ONCE per kc (12 ldsm vs 18)
            ldsm4(ah[0], pAhi + aoff + koff);
            ldsm4(ah[1], pAhi + aoff + 16 * ROWB + koff);
            ldsm4(al[0], pAlo + aoff + koff);
            ldsm4(al[1], pAlo + aoff + 16 * ROWB + koff);
            #pragma unroll
            for (int p = 0; p < 4; p++)
                ldsm4(b[p], pBhi + boff + p * (16 * ROWB) + koff);
            // hi*hi + lo*hi with b_hi live
            #pragma unroll
            for (int n = 0; n < 8; n++) {
                uint32_t b0 = b[n >> 1][(n & 1) * 2];
                uint32_t b1 = b[n >> 1][(n & 1) * 2 + 1];
                mma16816(acc[0][n], ah[0], b0, b1);
                mma16816(acc[1][n], ah[1], b0, b1);
                mma16816(acc[0][n], al[0], b0, b1);
                mma16816(acc[1][n], al[1], b0, b1);
            }
            // reuse b registers for b_lo
            #pragma unroll
            for (int p = 0; p < 4; p++)
                ldsm4(b[p], pBlo + boff + p * (16 * ROWB) + koff);
            #pragma unroll
            for (int n = 0; n < 8; n++) {
                uint32_t b0 = b[n >> 1][(n & 1) * 2];
                uint32_t b1 = b[n >> 1][(n & 1) * 2 + 1];
                mma16816(acc[0][n], ah[0], b0, b1);
                mma16816(acc[1][n], ah[1], b0, b1);
            }
        }
        __syncthreads();
        if (it + 2 < nk) load_stage(sb, it + 2, tid, sA_hi, sA_lo, sB_hi, sB_lo, K_pad);
    }

    #pragma unroll
    for (int m = 0; m < 2; m++) {
        #pragma unroll
        for (int n = 0; n < 8; n++) {
            int cglob = bn + wn * 64 + n * 8 + (l & 3) * 2;
            float* Cp;
            int cc;
            float2 bv;
            if (c_sel == 3) {
                bool right = cglob >= HC;
                Cp = right ? g_xr : g_xl;
                cc = right ? cglob - HC : cglob;
                bv = *(const float2*)(g_bias2 + cglob);
            } else {
                Cp = g_cls;
                cc = cglob;
                bv = *(const float2*)(bias + cglob);
            }
            int stride = (c_sel == 3) ? HC : N_tot;
            int r0 = bm + wm * 32 + m * 16 + (l >> 2);
            #pragma unroll
            for (int hh = 0; hh < 2; hh++) {
                int row = r0 + hh * 8;
                if (row < M) {
                    float vx = acc[m][n][hh * 2    ] + bv.x;
                    float vy = acc[m][n][hh * 2 + 1] + bv.y;
                    if (act == 1) {
                        vx = vx > 0.f ? vx : expm1f(vx);
                        vy = vy > 0.f ? vy : expm1f(vy);
                    }
                    *(float2*)(Cp + (size_t)row * stride + cc) = make_float2(vx, vy);
                }
            }
        }
    }
}

// ---------------- edge_index dtype detection ----------------
__global__ void k_detect(const unsigned long long* __restrict__ ei64) {
    int is64 = 1;
    for (int i = 0; i < 64; i++)
        if (ei64[i] >= (1ULL << 32)) { is64 = 0; break; }
    g_ei_is64 = is64;
}

// ---------------- CSR build ----------------
__global__ void k_zero_csr() {
    int i = blockIdx.x * blockDim.x + threadIdx.x;
    if (i < N_NODES) g_cnt[i] = 0;
}

__global__ void k_build(const void* __restrict__ ei) {
    int i = blockIdx.x * blockDim.x + threadIdx.x;
    if (i >= E_TOT) return;
    int s, d;
    if (i < N_EDGES) {
        if (g_ei_is64) {
            const long long* p = (const long long*)ei;
            s = (int)p[i]; d = (int)p[N_EDGES + i];
        } else {
            const int* p = (const int*)ei;
            s = p[i]; d = p[N_EDGES + i];
        }
    } else {
        s = d = i - N_EDGES;
    }
    if ((unsigned)s >= N_NODES) s = 0;
    if ((unsigned)d >= N_NODES) d = 0;
    g_src[i] = s;
    g_dst[i] = d;
    atomicAdd(&g_cnt[d], 1);
}

__global__ void k_scan() {
    __shared__ int wsum[32];
    __shared__ int carry_s;
    int tid = threadIdx.x;
    if (tid == 0) carry_s = 0;
    __syncthreads();
    for (int base = 0; base < N_NODES; base += 1024) {
        int i = base + tid;
        int v = (i < N_NODES) ? g_cnt[i] : 0;
        int incl = v;
        int lane = tid & 31, wid = tid >> 5;
        #pragma unroll
        for (int o = 1; o < 32; o <<= 1) {
            int t = __shfl_up_sync(0xffffffffu, incl, o);
            if (lane >= o) incl += t;
        }
        if (lane == 31) wsum[wid] = incl;
        __syncthreads();
        if (wid == 0) {
            int s = wsum[lane];
            #pragma unroll
            for (int o = 1; o < 32; o <<= 1) {
                int t = __shfl_up_sync(0xffffffffu, s, o);
                if (lane >= o) s += t;
            }
            wsum[lane] = s;
        }
        __syncthreads();
        int off = (wid > 0) ? wsum[wid - 1] : 0;
        int excl = carry_s + off + incl - v;
        if (i < N_NODES) { g_rowptr[i] = excl; g_cursor[i] = excl; }
        __syncthreads();
        if (tid == 0) carry_s += wsum[31];
        __syncthreads();
    }
    if (tid == 0) g_rowptr[N_NODES] = carry_s;
}

__global__ void k_scatter() {
    int e = blockIdx.x * blockDim.x + threadIdx.x;
    if (e >= E_TOT) return;
    int pos = atomicAdd(&g_cursor[g_dst[e]], 1);
    g_perm[pos] = e;
}

// ---------------- edge scores + fused exp (no max subtraction) ----------------
// softmax is shift-invariant; scores here are O(1..10) so exp is safe in fp32.
__global__ void k_edge_scores(const float* __restrict__ att) {
    int e = (blockIdx.x * blockDim.x + threadIdx.x) >> 5;
    int lane = threadIdx.x & 31;
    if (e >= E_TOT) return;
    int se = g_src[e], de = g_dst[e];
    const float4* pl = (const float4*)(g_xl + (size_t)se * HC);
    const float4* pr = (const float4*)(g_xr + (size_t)de * HC);
    const float4* pa = (const float4*)att;
    float acc[4] = {0.f, 0.f, 0.f, 0.f};
    #pragma unroll
    for (int i = 0; i < 8; i++) {
        int idx = i * 32 + lane;
        float4 a = pl[idx], b = pr[idx], t = pa[idx];
        float mx = a.x + b.x, my = a.y + b.y, mz = a.z + b.z, mw = a.w + b.w;
        mx = mx > 0.f ? mx : 0.2f * mx;
        my = my > 0.f ? my : 0.2f * my;
        mz = mz > 0.f ? mz : 0.2f * mz;
        mw = mw > 0.f ? mw : 0.2f * mw;
        acc[i >> 1] += mx * t.x + my * t.y + mz * t.z + mw * t.w;
    }
    #pragma unroll
    for (int h = 0; h < 4; h++) {
        float v = acc[h];
        #pragma unroll
        for (int o = 16; o; o >>= 1) v += __shfl_xor_sync(0xffffffffu, v, o);
        if (lane == 0) g_esc[e * 4 + h] = expf(v);
    }
}

// ---- fused aggregation + in-register den + LayerNorm + ELU + split-bf16 ----
__global__ __launch_bounds__(256)
void k_agg_ln(const float* __restrict__ bias,
              const float* __restrict__ w, const float* __restrict__ b) {
    int n = blockIdx.x;
    int tid = threadIdx.x;
    float acc[4] = {0.f, 0.f, 0.f, 0.f};
    float den[4] = {0.f, 0.f, 0.f, 0.f};
    int beg = g_rowptr[n], end = g_rowptr[n + 1];
    for (int j = beg; j < end; j++) {
        int e = g_perm[j];
        int s = g_src[e];
        float4 p = *(const float4*)&g_esc[e * 4];
        den[0] += p.x; den[1] += p.y; den[2] += p.z; den[3] += p.w;
        const float* row = g_xl + (size_t)s * HC;
        acc[0] = fmaf(p.x, row[tid      ], acc[0]);
        acc[1] = fmaf(p.y, row[tid + 256], acc[1]);
        acc[2] = fmaf(p.z, row[tid + 512], acc[2]);
        acc[3] = fmaf(p.w, row[tid + 768], acc[3]);
    }
    float v[4];
    float s = 0.f, s2 = 0.f;
    #pragma unroll
    for (int i = 0; i < 4; i++) {
        v[i] = acc[i] / (den[i] + 1e-16f) + bias[tid + i * 256];
        s += v[i];
        s2 += v[i] * v[i];
    }
    __shared__ float rs[8], rs2[8];
    int lane = tid & 31, wid = tid >> 5;
    #pragma unroll
    for (int o = 16; o; o >>= 1) {
        s  += __shfl_xor_sync(0xffffffffu, s,  o);
        s2 += __shfl_xor_sync(0xffffffffu, s2, o);
    }
    if (lane == 0) { rs[wid] = s; rs2[wid] = s2; }
    __syncthreads();
    if (tid == 0) {
        float a = 0.f, a2 = 0.f;
        #pragma unroll
        for (int i = 0; i < 8; i++) { a += rs[i]; a2 += rs2[i]; }
        rs[0] = a; rs2[0] = a2;
    }
    __syncthreads();
    float mu = rs[0] * (1.f / HC);
    float var = rs2[0] * (1.f / HC) - mu * mu;
    float r = rsqrtf(var + 1e-5f);
    size_t base = (size_t)n * KP2;
    #pragma unroll
    for (int i = 0; i < 4; i++) {
        int c = tid + i * 256;
        float y = (v[i] - mu) * r * w[c] + b[c];
        y = y > 0.f ? y : expm1f(y);
        __nv_bfloat16 hi = __float2bfloat16_rn(y);
        __nv_bfloat16 lo = __float2bfloat16_rn(y - __bfloat162float(hi));
        g_ahi[base + c] = hi;
        g_alo[base + c] = lo;
    }
}

// ---------------- classifier layer 2 (tiled: 32 nodes/block) ----------------
#define CLS_N   32
#define SMEM_CLS ((HID * OUT_CH + CLS_N * HID) * 4)
__global__ __launch_bounds__(256)
void k_cls2(const float* __restrict__ w2, const float* __restrict__ b2,
            float* __restrict__ out) {
    extern __shared__ float smc[];
    float* sw  = smc;
    float* shh = smc + HID * OUT_CH;
    int tid = threadIdx.x;
    int base = blockIdx.x * CLS_N;
    for (int i = tid; i < HID * OUT_CH; i += 256) sw[i] = w2[i];
    for (int i = tid; i < CLS_N * HID; i += 256) {
        int n = i >> 8, c = i & 255;
        int gn = base + n;
        shh[i] = (gn < N_NODES) ? g_cls[(size_t)gn * HID + c] : 0.f;
    }
    __syncthreads();
    int j = tid & 63, grp = tid >> 6;
    if (j < OUT_CH) {
        float bj = b2[j];
        for (int n = grp; n < CLS_N; n += 4) {
            int gn = base + n;
            if (gn >= N_NODES) break;
            const float4* hr = (const float4*)(shh + n * HID);
            float a = bj;
            #pragma unroll 16
            for (int k4 = 0; k4 < HID / 4; k4++) {
                float4 h4 = hr[k4];
                int k = k4 * 4;
                a = fmaf(h4.x, sw[(k    ) * OUT_CH + j], a);
                a = fmaf(h4.y, sw[(k + 1) * OUT_CH + j], a);
                a = fmaf(h4.z, sw[(k + 2) * OUT_CH + j], a);
                a = fmaf(h4.w, sw[(k + 3) * OUT_CH + j], a);
            }
            out[(size_t)gn * OUT_CH + j] = a;
        }
    }
}

// ---------------- launch ----------------
extern "C" void kernel_launch(void* const* d_in, const int* in_sizes, int n_in,
                              void* d_out, int out_size) {
    static const int MAP_INSERT[22] =
        {0,1,2,3,4,5,6,7,8,9,10,11,12,13,14,15,16,17,18,19,20,21};
    static const int MAP_ALPHA[22] =
        {21, 16, 4, 2, 5, 3, 0, 1, 18, 17,
         10, 8, 11, 9, 6, 7, 20, 19, 14, 12, 15, 13};
    const int* map = MAP_INSERT;
    if (n_in >= 22 && in_sizes[0] != N_NODES * IN_CH && in_sizes[21] == N_NODES * IN_CH)
        map = MAP_ALPHA;

    const float* x       = (const float*)d_in[map[0]];
    const void*  ei      = d_in[map[1]];
    const float* c1_wl   = (const float*)d_in[map[2]];
    const float* c1_bl   = (const float*)d_in[map[3]];
    const float* c1_wr   = (const float*)d_in[map[4]];
    const float* c1_br   = (const float*)d_in[map[5]];
    const float* c1_att  = (const float*)d_in[map[6]];
    const float* c1_bias = (const float*)d_in[map[7]];
    const float* ln1_w   = (const float*)d_in[map[8]];
    const float* ln1_b   = (const float*)d_in[map[9]];
    const float* c2_wl   = (const float*)d_in[map[10]];
    const float* c2_bl   = (const float*)d_in[map[11]];
    const float* c2_wr   = (const float*)d_in[map[12]];
    const float* c2_br   = (const float*)d_in[map[13]];
    const float* c2_att  = (const float*)d_in[map[14]];
    const float* c2_bias = (const float*)d_in[map[15]];
    const float* ln2_w   = (const float*)d_in[map[16]];
    const float* ln2_b   = (const float*)d_in[map[17]];
    const float* cls_w1  = (const float*)d_in[map[18]];
    const float* cls_b1  = (const float*)d_in[map[19]];
    const float* cls_w2  = (const float*)d_in[map[20]];
    const float* cls_b2  = (const float*)d_in[map[21]];
    float* out = (float*)d_out;

    cudaFuncSetAttribute(k_mma, cudaFuncAttributeMaxDynamicSharedMemorySize, SMEM_MMA);
    cudaFuncSetAttribute(k_cls2, cudaFuncAttributeMaxDynamicSharedMemorySize, SMEM_CLS);

    // CSR build
    k_detect<<<1, 1>>>((const unsigned long long*)ei);
    k_zero_csr<<<(N_NODES + 255) / 256, 256>>>();
    k_build<<<(E_TOT + 255) / 256, 256>>>(ei);
    k_scan<<<1, 1024>>>();
    k_scatter<<<(E_TOT + 255) / 256, 256>>>();

    int eb = (E_TOT + 7) / 8;
    const int CB = 256;
    size_t a1_tot = (size_t)M_PAD * KP1;
    size_t b2tot1 = (size_t)2 * HC * KP1, b2tot2 = (size_t)2 * HC * KP2;

    // ---- conv1 ----
    k_cvt_a<<<(int)((a1_tot + CB - 1) / CB), CB>>>(x, N_NODES, IN_CH, KP1, M_PAD);
    k_cvt_b2<<<(int)((b2tot1 + CB - 1) / CB), CB>>>(c1_wl, c1_wr, c1_bl, c1_br, IN_CH, KP1);
    {
        dim3 g(2 * HC / 128, (N_NODES + 127) / 128);
        k_mma<<<g, 256, SMEM_MMA>>>(3, nullptr, N_NODES, 2 * HC, KP1, 0);
    }
    k_edge_scores<<<eb, 256>>>(c1_att);
    k_agg_ln<<<N_NODES, 256>>>(c1_bias, ln1_w, ln1_b);

    // ---- conv2 ----
    k_cvt_b2<<<(int)((b2tot2 + CB - 1) / CB), CB>>>(c2_wl, c2_wr, c2_bl, c2_br, HC, KP2);
    {
        dim3 g(2 * HC / 128, (N_NODES + 127) / 128);
        k_mma<<<g, 256, SMEM_MMA>>>(3, nullptr, N_NODES, 2 * HC, KP2, 0);
    }
    k_edge_scores<<<eb, 256>>>(c2_att);
    k_agg_ln<<<N_NODES, 256>>>(c2_bias, ln2_w, ln2_b);

    // ---- classifier ----
    k_cvt_b<<<(int)(((size_t)HID * KP2 + CB - 1) / CB), CB>>>(cls_w1, HC, HID, KP2);
    {
        dim3 g(HID / 128, (N_NODES + 127) / 128);
        k_mma<<<g, 256, SMEM_MMA>>>(2, cls_b1, N_NODES, HID, KP2, 1);
    }
    k_cls2<<<(N_NODES + CLS_N - 1) / CLS_N, 256, SMEM_CLS>>>(cls_w2, cls_b2, out);
}

// round 13
// speedup vs baseline: 2.7978x; 1.0009x over previous
#include <cuda_runtime.h>
#include <cuda_bf16.h>
#include <math.h>
#include <stdint.h>

#define N_NODES 10000
#define N_EDGES 160000
#define E_TOT   170000
#define IN_CH   1030
#define HC      1024
#define HID     256
#define OUT_CH  49
#define M_PAD   10112
#define KP1     1088
#define KP2     1024

// ---------------- device scratch ----------------
__device__ float g_xl[(size_t)N_NODES * HC];
__device__ float g_xr[(size_t)N_NODES * HC];
__device__ float g_cls[(size_t)N_NODES * HID];
__device__ float g_bias2[2 * HC];
__device__ __align__(128) __nv_bfloat16 g_ahi[(size_t)M_PAD * KP1];
__device__ __align__(128) __nv_bfloat16 g_alo[(size_t)M_PAD * KP1];
__device__ __align__(128) __nv_bfloat16 g_bhi[(size_t)2 * HC * KP1];
__device__ __align__(128) __nv_bfloat16 g_blo[(size_t)2 * HC * KP1];
__device__ int      g_src[E_TOT];
__device__ int      g_dst[E_TOT];
__device__ float    g_esc[E_TOT * 4];
__device__ int g_cnt[N_NODES];
__device__ int g_rowptr[N_NODES + 1];
__device__ int g_cursor[N_NODES];
__device__ int g_perm[E_TOT];
__device__ int g_ei_is64;

// ---------------- asm helpers ----------------
__device__ __forceinline__ uint32_t smem_u32(const void* p) {
    uint32_t a;
    asm("{ .reg .u64 t; cvta.to.shared.u64 t, %1; cvt.u32.u64 %0, t; }" : "=r"(a) : "l"(p));
    return a;
}
__device__ __forceinline__ void cp_async16(uint32_t dst, const void* src) {
    asm volatile("cp.async.cg.shared.global [%0], [%1], 16;" :: "r"(dst), "l"(src));
}
#define CP_COMMIT() asm volatile("cp.async.commit_group;")
#define CP_WAIT0()  asm volatile("cp.async.wait_group 0;" ::: "memory")
#define CP_WAIT1()  asm volatile("cp.async.wait_group 1;" ::: "memory")

__device__ __forceinline__ void ldsm4(uint32_t* r, uint32_t addr) {
    asm volatile("ldmatrix.sync.aligned.m8n8.x4.shared.b16 {%0,%1,%2,%3}, [%4];"
        : "=r"(r[0]), "=r"(r[1]), "=r"(r[2]), "=r"(r[3]) : "r"(addr));
}
__device__ __forceinline__ void mma16816(float* c, const uint32_t* a,
                                         uint32_t b0, uint32_t b1) {
    asm volatile(
        "mma.sync.aligned.m16n8k16.row.col.f32.bf16.bf16.f32 "
        "{%0,%1,%2,%3}, {%4,%5,%6,%7}, {%8,%9}, {%0,%1,%2,%3};"
        : "+f"(c[0]), "+f"(c[1]), "+f"(c[2]), "+f"(c[3])
        : "r"(a[0]), "r"(a[1]), "r"(a[2]), "r"(a[3]), "r"(b0), "r"(b1));
}

// ---------------- conversions ----------------
__global__ void k_cvt_a(const float* __restrict__ A, int M_real, int K_real,
                        int K_pad, int M_use) {
    size_t idx = (size_t)blockIdx.x * blockDim.x + threadIdx.x;
    size_t tot = (size_t)M_use * K_pad;
    if (idx >= tot) return;
    int r = (int)(idx / K_pad), c = (int)(idx % K_pad);
    float x = (r < M_real && c < K_real) ? A[(size_t)r * K_real + c] : 0.f;
    __nv_bfloat16 hi = __float2bfloat16_rn(x);
    __nv_bfloat16 lo = __float2bfloat16_rn(x - __bfloat162float(hi));
    g_ahi[idx] = hi;
    g_alo[idx] = lo;
}

__global__ void k_cvt_b2(const float* __restrict__ Bl, const float* __restrict__ Br,
                         const float* __restrict__ bl, const float* __restrict__ br,
                         int K_real, int K_pad) {
    size_t idx = (size_t)blockIdx.x * blockDim.x + threadIdx.x;
    if (idx < 2 * HC) g_bias2[idx] = (idx < HC) ? bl[idx] : br[idx - HC];
    size_t tot = (size_t)2 * HC * K_pad;
    if (idx >= tot) return;
    int n = (int)(idx / K_pad), k = (int)(idx % K_pad);
    const float* B = (n < HC) ? Bl : Br;
    int nn = (n < HC) ? n : n - HC;
    float x = (k < K_real) ? B[(size_t)k * HC + nn] : 0.f;
    __nv_bfloat16 hi = __float2bfloat16_rn(x);
    __nv_bfloat16 lo = __float2bfloat16_rn(x - __bfloat162float(hi));
    g_bhi[idx] = hi;
    g_blo[idx] = lo;
}

__global__ void k_cvt_b(const float* __restrict__ B, int K_real, int N, int K_pad) {
    size_t idx = (size_t)blockIdx.x * blockDim.x + threadIdx.x;
    size_t tot = (size_t)N * K_pad;
    if (idx >= tot) return;
    int n = (int)(idx / K_pad), k = (int)(idx % K_pad);
    float x = (k < K_real) ? B[(size_t)k * N + n] : 0.f;
    __nv_bfloat16 hi = __float2bfloat16_rn(x);
    __nv_bfloat16 lo = __float2bfloat16_rn(x - __bfloat162float(hi));
    g_bhi[idx] = hi;
    g_blo[idx] = lo;
}

// ---------------- mma.sync split-bf16 GEMM ----------------
#define ROWB   80
#define TIL    (128 * ROWB)
#define STG    (4 * TIL)        // 40960
#define SMEM_MMA (2 * STG)      // 80KB -> 2 CTA/SM

__device__ __forceinline__ void load_stage(uint32_t sb, int it, int tid,
                                           const __nv_bfloat16* s0, const __nv_bfloat16* s1,
                                           const __nv_bfloat16* s2, const __nv_bfloat16* s3,
                                           int K_pad) {
    uint32_t stage = sb + (uint32_t)(it & 1) * STG;
    int k0 = it * 32;
    const __nv_bfloat16* srcs[4] = {s0, s1, s2, s3};
    #pragma unroll
    for (int q = 0; q < 8; q++) {
        int id = tid + q * 256;
        int t = id >> 9, r = (id >> 2) & 127, u = id & 3;
        cp_async16(stage + t * TIL + r * ROWB + u * 16,
                   srcs[t] + (size_t)r * K_pad + k0 + u * 8);
    }
    CP_COMMIT();
}

// c_sel: 2 = g_cls (bias, act), 3 = split g_xl/g_xr (g_bias2)
__global__ __launch_bounds__(256)
void k_mma(int c_sel, const float* __restrict__ bias,
           int M, int N_tot, int K_pad, int act) {
    extern __shared__ char sm[];
    int tid = threadIdx.x, w = tid >> 5, l = tid & 31;
    int wm = w >> 1, wn = w & 1;
    int bm = blockIdx.y * 128, bn = blockIdx.x * 128;
    uint32_t sb = smem_u32(sm);
    int q = l >> 3;

    uint32_t aoff = (uint32_t)((wm * 32 + ((q & 1) << 3) + (l & 7)) * ROWB + ((q >> 1) << 4));
    uint32_t boff = (uint32_t)((wn * 64 + ((q >> 1) << 3) + (l & 7)) * ROWB + ((q & 1) << 4));

    const __nv_bfloat16* sA_hi = g_ahi + (size_t)bm * K_pad;
    const __nv_bfloat16* sA_lo = g_alo + (size_t)bm * K_pad;
    const __nv_bfloat16* sB_hi = g_bhi + (size_t)bn * K_pad;
    const __nv_bfloat16* sB_lo = g_blo + (size_t)bn * K_pad;

    float acc[2][8][4];
    #pragma unroll
    for (int m = 0; m < 2; m++)
        #pragma unroll
        for (int n = 0; n < 8; n++)
            #pragma unroll
            for (int i = 0; i < 4; i++) acc[m][n][i] = 0.f;

    int nk = K_pad / 32;
    load_stage(sb, 0, tid, sA_hi, sA_lo, sB_hi, sB_lo, K_pad);
    load_stage(sb, 1, tid, sA_hi, sA_lo, sB_hi, sB_lo, K_pad);

    for (int it = 0; it < nk; it++) {
        if (it == nk - 1) { CP_WAIT0(); } else { CP_WAIT1(); }
        __syncthreads();
        uint32_t stage = sb + (uint32_t)(it & 1) * STG;
        uint32_t pAhi = stage, pAlo = stage + TIL;
        uint32_t pBhi = stage + 2u * TIL, pBlo = stage + 3u * TIL;
        #pragma unroll
        for (int kc = 0; kc < 2; kc++) {
            uint32_t koff = kc * 32;
            uint32_t ah[2][4], al[2][4], b[4][4];
            // load each fragment set ONCE per kc (12 ldsm vs 18)
            ldsm4(ah[0], pAhi + aoff + koff);
            ldsm4(ah[1], pAhi + aoff + 16 * ROWB + koff);
            ldsm4(al[0], pAlo + aoff + koff);
            ldsm4(al[1], pAlo + aoff + 16 * ROWB + koff);
            #pragma unroll
            for (int p = 0; p < 4; p++)
                ldsm4(b[p], pBhi + boff + p * (16 * ROWB) + koff);
            // hi*hi + lo*hi with b_hi live
            #pragma unroll
            for (int n = 0; n < 8; n++) {
                uint32_t b0 = b[n >> 1][(n & 1) * 2];
                uint32_t b1 = b[n >> 1][(n & 1) * 2 + 1];
                mma16816(acc[0][n], ah[0], b0, b1);
                mma16816(acc[1][n], ah[1], b0, b1);
                mma16816(acc[0][n], al[0], b0, b1);
                mma16816(acc[1][n], al[1], b0, b1);
            }
            // reuse b registers for b_lo
            #pragma unroll
            for (int p = 0; p < 4; p++)
                ldsm4(b[p], pBlo + boff + p * (16 * ROWB) + koff);
            #pragma unroll
            for (int n = 0; n < 8; n++) {
                uint32_t b0 = b[n >> 1][(n & 1) * 2];
                uint32_t b1 = b[n >> 1][(n & 1) * 2 + 1];
                mma16816(acc[0][n], ah[0], b0, b1);
                mma16816(acc[1][n], ah[1], b0, b1);
            }
        }
        __syncthreads();
        if (it + 2 < nk) load_stage(sb, it + 2, tid, sA_hi, sA_lo, sB_hi, sB_lo, K_pad);
    }

    #pragma unroll
    for (int m = 0; m < 2; m++) {
        #pragma unroll
        for (int n = 0; n < 8; n++) {
            int cglob = bn + wn * 64 + n * 8 + (l & 3) * 2;
            float* Cp;
            int cc;
            float2 bv;
            if (c_sel == 3) {
                bool right = cglob >= HC;
                Cp = right ? g_xr : g_xl;
                cc = right ? cglob - HC : cglob;
                bv = *(const float2*)(g_bias2 + cglob);
            } else {
                Cp = g_cls;
                cc = cglob;
                bv = *(const float2*)(bias + cglob);
            }
            int stride = (c_sel == 3) ? HC : N_tot;
            int r0 = bm + wm * 32 + m * 16 + (l >> 2);
            #pragma unroll
            for (int hh = 0; hh < 2; hh++) {
                int row = r0 + hh * 8;
                if (row < M) {
                    float vx = acc[m][n][hh * 2    ] + bv.x;
                    float vy = acc[m][n][hh * 2 + 1] + bv.y;
                    if (act == 1) {
                        vx = vx > 0.f ? vx : expm1f(vx);
                        vy = vy > 0.f ? vy : expm1f(vy);
                    }
                    *(float2*)(Cp + (size_t)row * stride + cc) = make_float2(vx, vy);
                }
            }
        }
    }
}

// ---------------- edge_index dtype detection ----------------
__global__ void k_detect(const unsigned long long* __restrict__ ei64) {
    int is64 = 1;
    for (int i = 0; i < 64; i++)
        if (ei64[i] >= (1ULL << 32)) { is64 = 0; break; }
    g_ei_is64 = is64;
}

// ---------------- CSR build ----------------
__global__ void k_zero_csr() {
    int i = blockIdx.x * blockDim.x + threadIdx.x;
    if (i < N_NODES) g_cnt[i] = 0;
}

__global__ void k_build(const void* __restrict__ ei) {
    int i = blockIdx.x * blockDim.x + threadIdx.x;
    if (i >= E_TOT) return;
    int s, d;
    if (i < N_EDGES) {
        if (g_ei_is64) {
            const long long* p = (const long long*)ei;
            s = (int)p[i]; d = (int)p[N_EDGES + i];
        } else {
            const int* p = (const int*)ei;
            s = p[i]; d = p[N_EDGES + i];
        }
    } else {
        s = d = i - N_EDGES;
    }
    if ((unsigned)s >= N_NODES) s = 0;
    if ((unsigned)d >= N_NODES) d = 0;
    g_src[i] = s;
    g_dst[i] = d;
    atomicAdd(&g_cnt[d], 1);
}

__global__ void k_scan() {
    __shared__ int wsum[32];
    __shared__ int carry_s;
    int tid = threadIdx.x;
    if (tid == 0) carry_s = 0;
    __syncthreads();
    for (int base = 0; base < N_NODES; base += 1024) {
        int i = base + tid;
        int v = (i < N_NODES) ? g_cnt[i] : 0;
        int incl = v;
        int lane = tid & 31, wid = tid >> 5;
        #pragma unroll
        for (int o = 1; o < 32; o <<= 1) {
            int t = __shfl_up_sync(0xffffffffu, incl, o);
            if (lane >= o) incl += t;
        }
        if (lane == 31) wsum[wid] = incl;
        __syncthreads();
        if (wid == 0) {
            int s = wsum[lane];
            #pragma unroll
            for (int o = 1; o < 32; o <<= 1) {
                int t = __shfl_up_sync(0xffffffffu, s, o);
                if (lane >= o) s += t;
            }
            wsum[lane] = s;
        }
        __syncthreads();
        int off = (wid > 0) ? wsum[wid - 1] : 0;
        int excl = carry_s + off + incl - v;
        if (i < N_NODES) { g_rowptr[i] = excl; g_cursor[i] = excl; }
        __syncthreads();
        if (tid == 0) carry_s += wsum[31];
        __syncthreads();
    }
    if (tid == 0) g_rowptr[N_NODES] = carry_s;
}

__global__ void k_scatter() {
    int e = blockIdx.x * blockDim.x + threadIdx.x;
    if (e >= E_TOT) return;
    int pos = atomicAdd(&g_cursor[g_dst[e]], 1);
    g_perm[pos] = e;
}

// ---------------- edge scores + fused exp (no max subtraction) ----------------
// softmax is shift-invariant; scores here are O(1..10) so exp is safe in fp32.
__global__ void k_edge_scores(const float* __restrict__ att) {
    int e = (blockIdx.x * blockDim.x + threadIdx.x) >> 5;
    int lane = threadIdx.x & 31;
    if (e >= E_TOT) return;
    int se = g_src[e], de = g_dst[e];
    const float4* pl = (const float4*)(g_xl + (size_t)se * HC);
    const float4* pr = (const float4*)(g_xr + (size_t)de * HC);
    const float4* pa = (const float4*)att;
    float acc[4] = {0.f, 0.f, 0.f, 0.f};
    #pragma unroll
    for (int i = 0; i < 8; i++) {
        int idx = i * 32 + lane;
        float4 a = pl[idx], b = pr[idx], t = pa[idx];
        float mx = a.x + b.x, my = a.y + b.y, mz = a.z + b.z, mw = a.w + b.w;
        mx = mx > 0.f ? mx : 0.2f * mx;
        my = my > 0.f ? my : 0.2f * my;
        mz = mz > 0.f ? mz : 0.2f * mz;
        mw = mw > 0.f ? mw : 0.2f * mw;
        acc[i >> 1] += mx * t.x + my * t.y + mz * t.z + mw * t.w;
    }
    #pragma unroll
    for (int h = 0; h < 4; h++) {
        float v = acc[h];
        #pragma unroll
        for (int o = 16; o; o >>= 1) v += __shfl_xor_sync(0xffffffffu, v, o);
        if (lane == 0) g_esc[e * 4 + h] = expf(v);
    }
}

// ---- fused aggregation + in-register den + LayerNorm + ELU + split-bf16 ----
__global__ __launch_bounds__(256)
void k_agg_ln(const float* __restrict__ bias,
              const float* __restrict__ w, const float* __restrict__ b) {
    int n = blockIdx.x;
    int tid = threadIdx.x;
    float acc[4] = {0.f, 0.f, 0.f, 0.f};
    float den[4] = {0.f, 0.f, 0.f, 0.f};
    int beg = g_rowptr[n], end = g_rowptr[n + 1];
    for (int j = beg; j < end; j++) {
        int e = g_perm[j];
        int s = g_src[e];
        float4 p = *(const float4*)&g_esc[e * 4];
        den[0] += p.x; den[1] += p.y; den[2] += p.z; den[3] += p.w;
        const float* row = g_xl + (size_t)s * HC;
        acc[0] = fmaf(p.x, row[tid      ], acc[0]);
        acc[1] = fmaf(p.y, row[tid + 256], acc[1]);
        acc[2] = fmaf(p.z, row[tid + 512], acc[2]);
        acc[3] = fmaf(p.w, row[tid + 768], acc[3]);
    }
    float v[4];
    float s = 0.f, s2 = 0.f;
    #pragma unroll
    for (int i = 0; i < 4; i++) {
        v[i] = acc[i] / (den[i] + 1e-16f) + bias[tid + i * 256];
        s += v[i];
        s2 += v[i] * v[i];
    }
    __shared__ float rs[8], rs2[8];
    int lane = tid & 31, wid = tid >> 5;
    #pragma unroll
    for (int o = 16; o; o >>= 1) {
        s  += __shfl_xor_sync(0xffffffffu, s,  o);
        s2 += __shfl_xor_sync(0xffffffffu, s2, o);
    }
    if (lane == 0) { rs[wid] = s; rs2[wid] = s2; }
    __syncthreads();
    if (tid == 0) {
        float a = 0.f, a2 = 0.f;
        #pragma unroll
        for (int i = 0; i < 8; i++) { a += rs[i]; a2 += rs2[i]; }
        rs[0] = a; rs2[0] = a2;
    }
    __syncthreads();
    float mu = rs[0] * (1.f / HC);
    float var = rs2[0] * (1.f / HC) - mu * mu;
    float r = rsqrtf(var + 1e-5f);
    size_t base = (size_t)n * KP2;
    #pragma unroll
    for (int i = 0; i < 4; i++) {
        int c = tid + i * 256;
        float y = (v[i] - mu) * r * w[c] + b[c];
        y = y > 0.f ? y : expm1f(y);
        __nv_bfloat16 hi = __float2bfloat16_rn(y);
        __nv_bfloat16 lo = __float2bfloat16_rn(y - __bfloat162float(hi));
        g_ahi[base + c] = hi;
        g_alo[base + c] = lo;
    }
}

// ---------------- classifier layer 2 (tiled: 32 nodes/block) ----------------
#define CLS_N   32
#define SMEM_CLS ((HID * OUT_CH + CLS_N * HID) * 4)
__global__ __launch_bounds__(256)
void k_cls2(const float* __restrict__ w2, const float* __restrict__ b2,
            float* __restrict__ out) {
    extern __shared__ float smc[];
    float* sw  = smc;
    float* shh = smc + HID * OUT_CH;
    int tid = threadIdx.x;
    int base = blockIdx.x * CLS_N;
    for (int i = tid; i < HID * OUT_CH; i += 256) sw[i] = w2[i];
    for (int i = tid; i < CLS_N * HID; i += 256) {
        int n = i >> 8, c = i & 255;
        int gn = base + n;
        shh[i] = (gn < N_NODES) ? g_cls[(size_t)gn * HID + c] : 0.f;
    }
    __syncthreads();
    int j = tid & 63, grp = tid >> 6;
    if (j < OUT_CH) {
        float bj = b2[j];
        for (int n = grp; n < CLS_N; n += 4) {
            int gn = base + n;
            if (gn >= N_NODES) break;
            const float4* hr = (const float4*)(shh + n * HID);
            float a = bj;
            #pragma unroll 16
            for (int k4 = 0; k4 < HID / 4; k4++) {
                float4 h4 = hr[k4];
                int k = k4 * 4;
                a = fmaf(h4.x, sw[(k    ) * OUT_CH + j], a);
                a = fmaf(h4.y, sw[(k + 1) * OUT_CH + j], a);
                a = fmaf(h4.z, sw[(k + 2) * OUT_CH + j], a);
                a = fmaf(h4.w, sw[(k + 3) * OUT_CH + j], a);
            }
            out[(size_t)gn * OUT_CH + j] = a;
        }
    }
}

// ---------------- launch ----------------
extern "C" void kernel_launch(void* const* d_in, const int* in_sizes, int n_in,
                              void* d_out, int out_size) {
    static const int MAP_INSERT[22] =
        {0,1,2,3,4,5,6,7,8,9,10,11,12,13,14,15,16,17,18,19,20,21};
    static const int MAP_ALPHA[22] =
        {21, 16, 4, 2, 5, 3, 0, 1, 18, 17,
         10, 8, 11, 9, 6, 7, 20, 19, 14, 12, 15, 13};
    const int* map = MAP_INSERT;
    if (n_in >= 22 && in_sizes[0] != N_NODES * IN_CH && in_sizes[21] == N_NODES * IN_CH)
        map = MAP_ALPHA;

    const float* x       = (const float*)d_in[map[0]];
    const void*  ei      = d_in[map[1]];
    const float* c1_wl   = (const float*)d_in[map[2]];
    const float* c1_bl   = (const float*)d_in[map[3]];
    const float* c1_wr   = (const float*)d_in[map[4]];
    const float* c1_br   = (const float*)d_in[map[5]];
    const float* c1_att  = (const float*)d_in[map[6]];
    const float* c1_bias = (const float*)d_in[map[7]];
    const float* ln1_w   = (const float*)d_in[map[8]];
    const float* ln1_b   = (const float*)d_in[map[9]];
    const float* c2_wl   = (const float*)d_in[map[10]];
    const float* c2_bl   = (const float*)d_in[map[11]];
    const float* c2_wr   = (const float*)d_in[map[12]];
    const float* c2_br   = (const float*)d_in[map[13]];
    const float* c2_att  = (const float*)d_in[map[14]];
    const float* c2_bias = (const float*)d_in[map[15]];
    const float* ln2_w   = (const float*)d_in[map[16]];
    const float* ln2_b   = (const float*)d_in[map[17]];
    const float* cls_w1  = (const float*)d_in[map[18]];
    const float* cls_b1  = (const float*)d_in[map[19]];
    const float* cls_w2  = (const float*)d_in[map[20]];
    const float* cls_b2  = (const float*)d_in[map[21]];
    float* out = (float*)d_out;

    cudaFuncSetAttribute(k_mma, cudaFuncAttributeMaxDynamicSharedMemorySize, SMEM_MMA);
    cudaFuncSetAttribute(k_cls2, cudaFuncAttributeMaxDynamicSharedMemorySize, SMEM_CLS);

    // CSR build
    k_detect<<<1, 1>>>((const unsigned long long*)ei);
    k_zero_csr<<<(N_NODES + 255) / 256, 256>>>();
    k_build<<<(E_TOT + 255) / 256, 256>>>(ei);
    k_scan<<<1, 1024>>>();
    k_scatter<<<(E_TOT + 255) / 256, 256>>>();

    int eb = (E_TOT + 7) / 8;
    const int CB = 256;
    size_t a1_tot = (size_t)M_PAD * KP1;
    size_t b2tot1 = (size_t)2 * HC * KP1, b2tot2 = (size_t)2 * HC * KP2;

    // ---- conv1 ----
    k_cvt_a<<<(int)((a1_tot + CB - 1) / CB), CB>>>(x, N_NODES, IN_CH, KP1, M_PAD);
    k_cvt_b2<<<(int)((b2tot1 + CB - 1) / CB), CB>>>(c1_wl, c1_wr, c1_bl, c1_br, IN_CH, KP1);
    {
        dim3 g(2 * HC / 128, (N_NODES + 127) / 128);
        k_mma<<<g, 256, SMEM_MMA>>>(3, nullptr, N_NODES, 2 * HC, KP1, 0);
    }
    k_edge_scores<<<eb, 256>>>(c1_att);
    k_agg_ln<<<N_NODES, 256>>>(c1_bias, ln1_w, ln1_b);

    // ---- conv2 ----
    k_cvt_b2<<<(int)((b2tot2 + CB - 1) / CB), CB>>>(c2_wl, c2_wr, c2_bl, c2_br, HC, KP2);
    {
        dim3 g(2 * HC / 128, (N_NODES + 127) / 128);
        k_mma<<<g, 256, SMEM_MMA>>>(3, nullptr, N_NODES, 2 * HC, KP2, 0);
    }
    k_edge_scores<<<eb, 256>>>(c2_att);
    k_agg_ln<<<N_NODES, 256>>>(c2_bias, ln2_w, ln2_b);

    // ---- classifier ----
    k_cvt_b<<<(int)(((size_t)HID * KP2 + CB - 1) / CB), CB>>>(cls_w1, HC, HID, KP2);
    {
        dim3 g(HID / 128, (N_NODES + 127) / 128);
        k_mma<<<g, 256, SMEM_MMA>>>(2, cls_b1, N_NODES, HID, KP2, 1);
    }
    k_cls2<<<(N_NODES + CLS_N - 1) / CLS_N, 256, SMEM_CLS>>>(cls_w2, cls_b2, out);
}

// round 14
// speedup vs baseline: 3.8896x; 1.3903x over previous
#include <cuda_runtime.h>
#include <cuda_fp16.h>
#include <math.h>
#include <stdint.h>

#define N_NODES 10000
#define N_EDGES 160000
#define E_TOT   170000
#define IN_CH   1030
#define HC      1024
#define HID     256
#define OUT_CH  49
#define M_PAD   10112
#define KP1     1056          // 33*32 >= 1030
#define KP2     1024

// ---------------- device scratch ----------------
__device__ float g_xl[(size_t)N_NODES * HC];
__device__ float g_xr[(size_t)N_NODES * HC];
__device__ float g_cls[(size_t)N_NODES * HID];
__device__ float g_bias2[2 * HC];
__device__ __align__(128) __half g_ahi[(size_t)M_PAD * KP1];
__device__ __align__(128) __half g_alo[(size_t)M_PAD * KP1];
__device__ __align__(128) __half g_bh [(size_t)2 * HC * KP1];
__device__ int      g_src[E_TOT];
__device__ int      g_dst[E_TOT];
__device__ float    g_esc[E_TOT * 4];
__device__ int g_cnt[N_NODES];
__device__ int g_rowptr[N_NODES + 1];
__device__ int g_cursor[N_NODES];
__device__ int g_perm[E_TOT];
__device__ int g_ei_is64;

// ---------------- asm helpers ----------------
__device__ __forceinline__ uint32_t smem_u32(const void* p) {
    uint32_t a;
    asm("{ .reg .u64 t; cvta.to.shared.u64 t, %1; cvt.u32.u64 %0, t; }" : "=r"(a) : "l"(p));
    return a;
}
__device__ __forceinline__ void cp_async16(uint32_t dst, const void* src) {
    asm volatile("cp.async.cg.shared.global [%0], [%1], 16;" :: "r"(dst), "l"(src));
}
#define CP_COMMIT() asm volatile("cp.async.commit_group;")
#define CP_WAIT0()  asm volatile("cp.async.wait_group 0;" ::: "memory")
#define CP_WAIT1()  asm volatile("cp.async.wait_group 1;" ::: "memory")

__device__ __forceinline__ void ldsm4(uint32_t* r, uint32_t addr) {
    asm volatile("ldmatrix.sync.aligned.m8n8.x4.shared.b16 {%0,%1,%2,%3}, [%4];"
        : "=r"(r[0]), "=r"(r[1]), "=r"(r[2]), "=r"(r[3]) : "r"(addr));
}
__device__ __forceinline__ void mma16816(float* c, const uint32_t* a,
                                         uint32_t b0, uint32_t b1) {
    asm volatile(
        "mma.sync.aligned.m16n8k16.row.col.f32.f16.f16.f32 "
        "{%0,%1,%2,%3}, {%4,%5,%6,%7}, {%8,%9}, {%0,%1,%2,%3};"
        : "+f"(c[0]), "+f"(c[1]), "+f"(c[2]), "+f"(c[3])
        : "r"(a[0]), "r"(a[1]), "r"(a[2]), "r"(a[3]), "r"(b0), "r"(b1));
}

// ---------------- conversions (fp32 -> split fp16 A, fp16 B) ----------------
__global__ void k_cvt_a(const float* __restrict__ A, int M_real, int K_real,
                        int K_pad, int M_use) {
    size_t idx = (size_t)blockIdx.x * blockDim.x + threadIdx.x;
    size_t tot = (size_t)M_use * K_pad;
    if (idx >= tot) return;
    int r = (int)(idx / K_pad), c = (int)(idx % K_pad);
    float x = (r < M_real && c < K_real) ? A[(size_t)r * K_real + c] : 0.f;
    __half hi = __float2half_rn(x);
    __half lo = __float2half_rn(x - __half2float(hi));
    g_ahi[idx] = hi;
    g_alo[idx] = lo;
}

__global__ void k_cvt_b2(const float* __restrict__ Bl, const float* __restrict__ Br,
                         const float* __restrict__ bl, const float* __restrict__ br,
                         int K_real, int K_pad) {
    size_t idx = (size_t)blockIdx.x * blockDim.x + threadIdx.x;
    if (idx < 2 * HC) g_bias2[idx] = (idx < HC) ? bl[idx] : br[idx - HC];
    size_t tot = (size_t)2 * HC * K_pad;
    if (idx >= tot) return;
    int n = (int)(idx / K_pad), k = (int)(idx % K_pad);
    const float* B = (n < HC) ? Bl : Br;
    int nn = (n < HC) ? n : n - HC;
    float x = (k < K_real) ? B[(size_t)k * HC + nn] : 0.f;
    g_bh[idx] = __float2half_rn(x);
}

__global__ void k_cvt_b(const float* __restrict__ B, int K_real, int N, int K_pad) {
    size_t idx = (size_t)blockIdx.x * blockDim.x + threadIdx.x;
    size_t tot = (size_t)N * K_pad;
    if (idx >= tot) return;
    int n = (int)(idx / K_pad), k = (int)(idx % K_pad);
    float x = (k < K_real) ? B[(size_t)k * N + n] : 0.f;
    g_bh[idx] = __float2half_rn(x);
}

// ---------------- mma.sync split-fp16 GEMM (2-pass) ----------------
#define ROWB   80
#define TIL    (128 * ROWB)     // 10240
#define STG    (3 * TIL)        // 30720 (Ahi, Alo, Bh)
#define SMEM_MMA (2 * STG)      // 61440 -> 2 CTA/SM

__device__ __forceinline__ void load_stage(uint32_t sb, int it, int tid,
                                           const __half* s0, const __half* s1,
                                           const __half* s2, int K_pad) {
    uint32_t stage = sb + (uint32_t)(it & 1) * STG;
    int k0 = it * 32;
    const __half* srcs[3] = {s0, s1, s2};
    #pragma unroll
    for (int q = 0; q < 6; q++) {
        int id = tid + q * 256;            // 3 tiles x 128 rows x 4 x 16B
        int t = id >> 9, r = (id >> 2) & 127, u = id & 3;
        cp_async16(stage + t * TIL + r * ROWB + u * 16,
                   srcs[t] + (size_t)r * K_pad + k0 + u * 8);
    }
    CP_COMMIT();
}

// c_sel: 2 = g_cls (bias, act), 3 = split g_xl/g_xr (g_bias2)
__global__ __launch_bounds__(256)
void k_mma(int c_sel, const float* __restrict__ bias,
           int M, int N_tot, int K_pad, int act) {
    extern __shared__ char sm[];
    int tid = threadIdx.x, w = tid >> 5, l = tid & 31;
    int wm = w >> 1, wn = w & 1;
    int bm = blockIdx.y * 128, bn = blockIdx.x * 128;
    uint32_t sb = smem_u32(sm);
    int q = l >> 3;

    uint32_t aoff = (uint32_t)((wm * 32 + ((q & 1) << 3) + (l & 7)) * ROWB + ((q >> 1) << 4));
    uint32_t boff = (uint32_t)((wn * 64 + ((q >> 1) << 3) + (l & 7)) * ROWB + ((q & 1) << 4));

    const __half* sA_hi = g_ahi + (size_t)bm * K_pad;
    const __half* sA_lo = g_alo + (size_t)bm * K_pad;
    const __half* sB    = g_bh  + (size_t)bn * K_pad;

    float acc[2][8][4];
    #pragma unroll
    for (int m = 0; m < 2; m++)
        #pragma unroll
        for (int n = 0; n < 8; n++)
            #pragma unroll
            for (int i = 0; i < 4; i++) acc[m][n][i] = 0.f;

    int nk = K_pad / 32;
    load_stage(sb, 0, tid, sA_hi, sA_lo, sB, K_pad);
    load_stage(sb, 1, tid, sA_hi, sA_lo, sB, K_pad);

    for (int it = 0; it < nk; it++) {
        if (it == nk - 1) { CP_WAIT0(); } else { CP_WAIT1(); }
        __syncthreads();
        uint32_t stage = sb + (uint32_t)(it & 1) * STG;
        uint32_t pAhi = stage, pAlo = stage + TIL, pB = stage + 2u * TIL;
        #pragma unroll
        for (int kc = 0; kc < 2; kc++) {
            uint32_t koff = kc * 32;
            uint32_t ah[2][4], al[2][4], b[4][4];
            ldsm4(ah[0], pAhi + aoff + koff);
            ldsm4(ah[1], pAhi + aoff + 16 * ROWB + koff);
            ldsm4(al[0], pAlo + aoff + koff);
            ldsm4(al[1], pAlo + aoff + 16 * ROWB + koff);
            #pragma unroll
            for (int p = 0; p < 4; p++)
                ldsm4(b[p], pB + boff + p * (16 * ROWB) + koff);
            #pragma unroll
            for (int n = 0; n < 8; n++) {
                uint32_t b0 = b[n >> 1][(n & 1) * 2];
                uint32_t b1 = b[n >> 1][(n & 1) * 2 + 1];
                mma16816(acc[0][n], ah[0], b0, b1);
                mma16816(acc[1][n], ah[1], b0, b1);
                mma16816(acc[0][n], al[0], b0, b1);
                mma16816(acc[1][n], al[1], b0, b1);
            }
        }
        __syncthreads();
        if (it + 2 < nk) load_stage(sb, it + 2, tid, sA_hi, sA_lo, sB, K_pad);
    }

    #pragma unroll
    for (int m = 0; m < 2; m++) {
        #pragma unroll
        for (int n = 0; n < 8; n++) {
            int cglob = bn + wn * 64 + n * 8 + (l & 3) * 2;
            float* Cp;
            int cc;
            float2 bv;
            if (c_sel == 3) {
                bool right = cglob >= HC;
                Cp = right ? g_xr : g_xl;
                cc = right ? cglob - HC : cglob;
                bv = *(const float2*)(g_bias2 + cglob);
            } else {
                Cp = g_cls;
                cc = cglob;
                bv = *(const float2*)(bias + cglob);
            }
            int stride = (c_sel == 3) ? HC : N_tot;
            int r0 = bm + wm * 32 + m * 16 + (l >> 2);
            #pragma unroll
            for (int hh = 0; hh < 2; hh++) {
                int row = r0 + hh * 8;
                if (row < M) {
                    float vx = acc[m][n][hh * 2    ] + bv.x;
                    float vy = acc[m][n][hh * 2 + 1] + bv.y;
                    if (act == 1) {
                        vx = vx > 0.f ? vx : expm1f(vx);
                        vy = vy > 0.f ? vy : expm1f(vy);
                    }
                    *(float2*)(Cp + (size_t)row * stride + cc) = make_float2(vx, vy);
                }
            }
        }
    }
}

// ---------------- edge_index dtype detection ----------------
__global__ void k_detect(const unsigned long long* __restrict__ ei64) {
    int is64 = 1;
    for (int i = 0; i < 64; i++)
        if (ei64[i] >= (1ULL << 32)) { is64 = 0; break; }
    g_ei_is64 = is64;
}

// ---------------- CSR build ----------------
__global__ void k_zero_csr() {
    int i = blockIdx.x * blockDim.x + threadIdx.x;
    if (i < N_NODES) g_cnt[i] = 0;
}

__global__ void k_build(const void* __restrict__ ei) {
    int i = blockIdx.x * blockDim.x + threadIdx.x;
    if (i >= E_TOT) return;
    int s, d;
    if (i < N_EDGES) {
        if (g_ei_is64) {
            const long long* p = (const long long*)ei;
            s = (int)p[i]; d = (int)p[N_EDGES + i];
        } else {
            const int* p = (const int*)ei;
            s = p[i]; d = p[N_EDGES + i];
        }
    } else {
        s = d = i - N_EDGES;
    }
    if ((unsigned)s >= N_NODES) s = 0;
    if ((unsigned)d >= N_NODES) d = 0;
    g_src[i] = s;
    g_dst[i] = d;
    atomicAdd(&g_cnt[d], 1);
}

__global__ void k_scan() {
    __shared__ int wsum[32];
    __shared__ int carry_s;
    int tid = threadIdx.x;
    if (tid == 0) carry_s = 0;
    __syncthreads();
    for (int base = 0; base < N_NODES; base += 1024) {
        int i = base + tid;
        int v = (i < N_NODES) ? g_cnt[i] : 0;
        int incl = v;
        int lane = tid & 31, wid = tid >> 5;
        #pragma unroll
        for (int o = 1; o < 32; o <<= 1) {
            int t = __shfl_up_sync(0xffffffffu, incl, o);
            if (lane >= o) incl += t;
        }
        if (lane == 31) wsum[wid] = incl;
        __syncthreads();
        if (wid == 0) {
            int s = wsum[lane];
            #pragma unroll
            for (int o = 1; o < 32; o <<= 1) {
                int t = __shfl_up_sync(0xffffffffu, s, o);
                if (lane >= o) s += t;
            }
            wsum[lane] = s;
        }
        __syncthreads();
        int off = (wid > 0) ? wsum[wid - 1] : 0;
        int excl = carry_s + off + incl - v;
        if (i < N_NODES) { g_rowptr[i] = excl; g_cursor[i] = excl; }
        __syncthreads();
        if (tid == 0) carry_s += wsum[31];
        __syncthreads();
    }
    if (tid == 0) g_rowptr[N_NODES] = carry_s;
}

__global__ void k_scatter() {
    int e = blockIdx.x * blockDim.x + threadIdx.x;
    if (e >= E_TOT) return;
    int pos = atomicAdd(&g_cursor[g_dst[e]], 1);
    g_perm[pos] = e;
}

// ---------------- edge scores + fused exp ----------------
__global__ void k_edge_scores(const float* __restrict__ att) {
    int e = (blockIdx.x * blockDim.x + threadIdx.x) >> 5;
    int lane = threadIdx.x & 31;
    if (e >= E_TOT) return;
    int se = g_src[e], de = g_dst[e];
    const float4* pl = (const float4*)(g_xl + (size_t)se * HC);
    const float4* pr = (const float4*)(g_xr + (size_t)de * HC);
    const float4* pa = (const float4*)att;
    float acc[4] = {0.f, 0.f, 0.f, 0.f};
    #pragma unroll
    for (int i = 0; i < 8; i++) {
        int idx = i * 32 + lane;
        float4 a = pl[idx], b = pr[idx], t = pa[idx];
        float mx = a.x + b.x, my = a.y + b.y, mz = a.z + b.z, mw = a.w + b.w;
        mx = mx > 0.f ? mx : 0.2f * mx;
        my = my > 0.f ? my : 0.2f * my;
        mz = mz > 0.f ? mz : 0.2f * mz;
        mw = mw > 0.f ? mw : 0.2f * mw;
        acc[i >> 1] += mx * t.x + my * t.y + mz * t.z + mw * t.w;
    }
    #pragma unroll
    for (int h = 0; h < 4; h++) {
        float v = acc[h];
        #pragma unroll
        for (int o = 16; o; o >>= 1) v += __shfl_xor_sync(0xffffffffu, v, o);
        if (lane == 0) g_esc[e * 4 + h] = expf(v);
    }
}

// ---- fused aggregation + LayerNorm + ELU + split-fp16 write ----
__global__ __launch_bounds__(256)
void k_agg_ln(const float* __restrict__ bias,
              const float* __restrict__ w, const float* __restrict__ b) {
    int n = blockIdx.x;
    int tid = threadIdx.x;
    float acc[4] = {0.f, 0.f, 0.f, 0.f};
    float den[4] = {0.f, 0.f, 0.f, 0.f};
    int beg = g_rowptr[n], end = g_rowptr[n + 1];
    for (int j = beg; j < end; j++) {
        int e = g_perm[j];
        int s = g_src[e];
        float4 p = *(const float4*)&g_esc[e * 4];
        den[0] += p.x; den[1] += p.y; den[2] += p.z; den[3] += p.w;
        const float* row = g_xl + (size_t)s * HC;
        acc[0] = fmaf(p.x, row[tid      ], acc[0]);
        acc[1] = fmaf(p.y, row[tid + 256], acc[1]);
        acc[2] = fmaf(p.z, row[tid + 512], acc[2]);
        acc[3] = fmaf(p.w, row[tid + 768], acc[3]);
    }
    float v[4];
    float s = 0.f, s2 = 0.f;
    #pragma unroll
    for (int i = 0; i < 4; i++) {
        v[i] = acc[i] / (den[i] + 1e-16f) + bias[tid + i * 256];
        s += v[i];
        s2 += v[i] * v[i];
    }
    __shared__ float rs[8], rs2[8];
    int lane = tid & 31, wid = tid >> 5;
    #pragma unroll
    for (int o = 16; o; o >>= 1) {
        s  += __shfl_xor_sync(0xffffffffu, s,  o);
        s2 += __shfl_xor_sync(0xffffffffu, s2, o);
    }
    if (lane == 0) { rs[wid] = s; rs2[wid] = s2; }
    __syncthreads();
    if (tid == 0) {
        float a = 0.f, a2 = 0.f;
        #pragma unroll
        for (int i = 0; i < 8; i++) { a += rs[i]; a2 += rs2[i]; }
        rs[0] = a; rs2[0] = a2;
    }
    __syncthreads();
    float mu = rs[0] * (1.f / HC);
    float var = rs2[0] * (1.f / HC) - mu * mu;
    float r = rsqrtf(var + 1e-5f);
    size_t base = (size_t)n * KP2;
    #pragma unroll
    for (int i = 0; i < 4; i++) {
        int c = tid + i * 256;
        float y = (v[i] - mu) * r * w[c] + b[c];
        y = y > 0.f ? y : expm1f(y);
        __half hi = __float2half_rn(y);
        __half lo = __float2half_rn(y - __half2float(hi));
        g_ahi[base + c] = hi;
        g_alo[base + c] = lo;
    }
}

// ---------------- classifier layer 2 ----------------
#define CLS_N   32
#define SMEM_CLS ((HID * OUT_CH + CLS_N * HID) * 4)
__global__ __launch_bounds__(256)
void k_cls2(const float* __restrict__ w2, const float* __restrict__ b2,
            float* __restrict__ out) {
    extern __shared__ float smc[];
    float* sw  = smc;
    float* shh = smc + HID * OUT_CH;
    int tid = threadIdx.x;
    int base = blockIdx.x * CLS_N;
    for (int i = tid; i < HID * OUT_CH; i += 256) sw[i] = w2[i];
    for (int i = tid; i < CLS_N * HID; i += 256) {
        int n = i >> 8, c = i & 255;
        int gn = base + n;
        shh[i] = (gn < N_NODES) ? g_cls[(size_t)gn * HID + c] : 0.f;
    }
    __syncthreads();
    int j = tid & 63, grp = tid >> 6;
    if (j < OUT_CH) {
        float bj = b2[j];
        for (int n = grp; n < CLS_N; n += 4) {
            int gn = base + n;
            if (gn >= N_NODES) break;
            const float4* hr = (const float4*)(shh + n * HID);
            float a = bj;
            #pragma unroll 16
            for (int k4 = 0; k4 < HID / 4; k4++) {
                float4 h4 = hr[k4];
                int k = k4 * 4;
                a = fmaf(h4.x, sw[(k    ) * OUT_CH + j], a);
                a = fmaf(h4.y, sw[(k + 1) * OUT_CH + j], a);
                a = fmaf(h4.z, sw[(k + 2) * OUT_CH + j], a);
                a = fmaf(h4.w, sw[(k + 3) * OUT_CH + j], a);
            }
            out[(size_t)gn * OUT_CH + j] = a;
        }
    }
}

// ---------------- launch ----------------
extern "C" void kernel_launch(void* const* d_in, const int* in_sizes, int n_in,
                              void* d_out, int out_size) {
    static const int MAP_INSERT[22] =
        {0,1,2,3,4,5,6,7,8,9,10,11,12,13,14,15,16,17,18,19,20,21};
    static const int MAP_ALPHA[22] =
        {21, 16, 4, 2, 5, 3, 0, 1, 18, 17,
         10, 8, 11, 9, 6, 7, 20, 19, 14, 12, 15, 13};
    const int* map = MAP_INSERT;
    if (n_in >= 22 && in_sizes[0] != N_NODES * IN_CH && in_sizes[21] == N_NODES * IN_CH)
        map = MAP_ALPHA;

    const float* x       = (const float*)d_in[map[0]];
    const void*  ei      = d_in[map[1]];
    const float* c1_wl   = (const float*)d_in[map[2]];
    const float* c1_bl   = (const float*)d_in[map[3]];
    const float* c1_wr   = (const float*)d_in[map[4]];
    const float* c1_br   = (const float*)d_in[map[5]];
    const float* c1_att  = (const float*)d_in[map[6]];
    const float* c1_bias = (const float*)d_in[map[7]];
    const float* ln1_w   = (const float*)d_in[map[8]];
    const float* ln1_b   = (const float*)d_in[map[9]];
    const float* c2_wl   = (const float*)d_in[map[10]];
    const float* c2_bl   = (const float*)d_in[map[11]];
    const float* c2_wr   = (const float*)d_in[map[12]];
    const float* c2_br   = (const float*)d_in[map[13]];
    const float* c2_att  = (const float*)d_in[map[14]];
    const float* c2_bias = (const float*)d_in[map[15]];
    const float* ln2_w   = (const float*)d_in[map[16]];
    const float* ln2_b   = (const float*)d_in[map[17]];
    const float* cls_w1  = (const float*)d_in[map[18]];
    const float* cls_b1  = (const float*)d_in[map[19]];
    const float* cls_w2  = (const float*)d_in[map[20]];
    const float* cls_b2  = (const float*)d_in[map[21]];
    float* out = (float*)d_out;

    cudaFuncSetAttribute(k_mma, cudaFuncAttributeMaxDynamicSharedMemorySize, SMEM_MMA);
    cudaFuncSetAttribute(k_cls2, cudaFuncAttributeMaxDynamicSharedMemorySize, SMEM_CLS);

    // CSR build
    k_detect<<<1, 1>>>((const unsigned long long*)ei);
    k_zero_csr<<<(N_NODES + 255) / 256, 256>>>();
    k_build<<<(E_TOT + 255) / 256, 256>>>(ei);
    k_scan<<<1, 1024>>>();
    k_scatter<<<(E_TOT + 255) / 256, 256>>>();

    int eb = (E_TOT + 7) / 8;
    const int CB = 256;
    size_t a1_tot = (size_t)M_PAD * KP1;
    size_t b2tot1 = (size_t)2 * HC * KP1, b2tot2 = (size_t)2 * HC * KP2;

    // ---- conv1 ----
    k_cvt_a<<<(int)((a1_tot + CB - 1) / CB), CB>>>(x, N_NODES, IN_CH, KP1, M_PAD);
    k_cvt_b2<<<(int)((b2tot1 + CB - 1) / CB), CB>>>(c1_wl, c1_wr, c1_bl, c1_br, IN_CH, KP1);
    {
        dim3 g(2 * HC / 128, (N_NODES + 127) / 128);
        k_mma<<<g, 256, SMEM_MMA>>>(3, nullptr, N_NODES, 2 * HC, KP1, 0);
    }
    k_edge_scores<<<eb, 256>>>(c1_att);
    k_agg_ln<<<N_NODES, 256>>>(c1_bias, ln1_w, ln1_b);

    // ---- conv2 ----
    k_cvt_b2<<<(int)((b2tot2 + CB - 1) / CB), CB>>>(c2_wl, c2_wr, c2_bl, c2_br, HC, KP2);
    {
        dim3 g(2 * HC / 128, (N_NODES + 127) / 128);
        k_mma<<<g, 256, SMEM_MMA>>>(3, nullptr, N_NODES, 2 * HC, KP2, 0);
    }
    k_edge_scores<<<eb, 256>>>(c2_att);
    k_agg_ln<<<N_NODES, 256>>>(c2_bias, ln2_w, ln2_b);

    // ---- classifier ----
    k_cvt_b<<<(int)(((size_t)HID * KP2 + CB - 1) / CB), CB>>>(cls_w1, HC, HID, KP2);
    {
        dim3 g(HID / 128, (N_NODES + 127) / 128);
        k_mma<<<g, 256, SMEM_MMA>>>(2, cls_b1, N_NODES, HID, KP2, 1);
    }
    k_cls2<<<(N_NODES + CLS_N - 1) / CLS_N, 256, SMEM_CLS>>>(cls_w2, cls_b2, out);
}